// round 11
// baseline (speedup 1.0000x reference)
#include <cuda_runtime.h>
#include <cuda_bf16.h>
#include <math.h>
#include <stdint.h>

#define N_TOK   4096
#define D_MODEL 1024
#define N_HEADS 16
#define HEAD_DIM 64

// 0.125 * log2(e): folded into Q at projection time so attention can use exp2.
#define Q_PRESCALE 0.18033688011112042f

// ---------------- device scratch (allocation-free rule) ----------------
__device__ __nv_bfloat16 g_xhi[N_TOK * D_MODEL];
__device__ __nv_bfloat16 g_xlo[N_TOK * D_MODEL];
__device__ __nv_bfloat16 g_whi[4][D_MODEL * D_MODEL];
__device__ __nv_bfloat16 g_wlo[4][D_MODEL * D_MODEL];
__device__ __nv_bfloat16 g_qhi[N_TOK * D_MODEL];
__device__ __nv_bfloat16 g_qlo[N_TOK * D_MODEL];
__device__ __nv_bfloat16 g_khi[N_TOK * D_MODEL];
__device__ __nv_bfloat16 g_klo[N_TOK * D_MODEL];   // dead (2-pass QK^T); kept for layout
__device__ __nv_bfloat16 g_vhi[N_TOK * D_MODEL];
__device__ __nv_bfloat16 g_vlo[N_TOK * D_MODEL];
__device__ __nv_bfloat16 g_chi[N_TOK * D_MODEL];
__device__ __nv_bfloat16 g_clo[N_TOK * D_MODEL];

// ---------------- PTX helpers (sm_80-compatible; NO tcgen05) ------------
__device__ __forceinline__ uint32_t smem_u32(const void* p) {
    uint32_t a;
    asm("{ .reg .u64 t; cvta.to.shared.u64 t, %1; cvt.u32.u64 %0, t; }" : "=r"(a) : "l"(p));
    return a;
}

#define CP16(s, g) \
    asm volatile("cp.async.cg.shared.global [%0], [%1], 16;" :: "r"(s), "l"(g))
#define CP_COMMIT() asm volatile("cp.async.commit_group;" ::: "memory")
#define CP_WAIT(n)  asm volatile("cp.async.wait_group %0;" :: "n"(n) : "memory")

#define LDMX4(r, addr) \
    asm volatile("ldmatrix.sync.aligned.m8n8.x4.shared.b16 {%0,%1,%2,%3}, [%4];" \
        : "=r"((r)[0]), "=r"((r)[1]), "=r"((r)[2]), "=r"((r)[3]) : "r"(addr))

#define LDMX4T(r, addr) \
    asm volatile("ldmatrix.sync.aligned.m8n8.x4.trans.shared.b16 {%0,%1,%2,%3}, [%4];" \
        : "=r"((r)[0]), "=r"((r)[1]), "=r"((r)[2]), "=r"((r)[3]) : "r"(addr))

#define MMA_BF16(d, a, b0, b1) \
    asm volatile("mma.sync.aligned.m16n8k16.row.col.f32.bf16.bf16.f32 " \
        "{%0,%1,%2,%3}, {%4,%5,%6,%7}, {%8,%9}, {%0,%1,%2,%3};" \
        : "+f"((d)[0]), "+f"((d)[1]), "+f"((d)[2]), "+f"((d)[3]) \
        : "r"((a)[0]), "r"((a)[1]), "r"((a)[2]), "r"((a)[3]), "r"(b0), "r"(b1))

__device__ __forceinline__ uint32_t pack_bf2(float a, float b) {
    uint32_t r;
    asm("cvt.rn.bf16x2.f32 %0, %1, %2;" : "=r"(r) : "f"(b), "f"(a));
    return r;
}
__device__ __forceinline__ float bfres(float x) {
    return x - __bfloat162float(__float2bfloat16(x));
}

// ---------------------------------------------------------------------------
// split fp32 -> bf16 hi + bf16 lo. x variant + fused 4-weight variant.
// ---------------------------------------------------------------------------
__global__ __launch_bounds__(256) void split_kernel(
    const float* __restrict__ src, __nv_bfloat16* __restrict__ hi,
    __nv_bfloat16* __restrict__ lo, int n)
{
    int i = (blockIdx.x * 256 + threadIdx.x) * 4;
    if (i >= n) return;
    float4 v = *(const float4*)(src + i);
    uint32_t* ph = (uint32_t*)(hi + i);
    uint32_t* pl = (uint32_t*)(lo + i);
    ph[0] = pack_bf2(v.x, v.y); ph[1] = pack_bf2(v.z, v.w);
    pl[0] = pack_bf2(bfres(v.x), bfres(v.y));
    pl[1] = pack_bf2(bfres(v.z), bfres(v.w));
}

__global__ __launch_bounds__(256) void split_w_kernel(
    const float* __restrict__ w0, const float* __restrict__ w1,
    const float* __restrict__ w2, const float* __restrict__ w3)
{
    const int sel = blockIdx.y;
    const float* src = (sel == 0) ? w0 : (sel == 1) ? w1 : (sel == 2) ? w2 : w3;
    const size_t NW = (size_t)D_MODEL * D_MODEL;
    __nv_bfloat16* hi = &g_whi[0][0] + sel * NW;
    __nv_bfloat16* lo = &g_wlo[0][0] + sel * NW;
    int i = (blockIdx.x * 256 + threadIdx.x) * 4;
    float4 v = *(const float4*)(src + i);
    uint32_t* ph = (uint32_t*)(hi + i);
    uint32_t* pl = (uint32_t*)(lo + i);
    ph[0] = pack_bf2(v.x, v.y); ph[1] = pack_bf2(v.z, v.w);
    pl[0] = pack_bf2(bfres(v.x), bfres(v.y));
    pl[1] = pack_bf2(bfres(v.z), bfres(v.w));
}

// ---------------------------------------------------------------------------
// Shared HMMA split-bf16 GEMM core: acc += A[m][k]*B[n][k], 3-pass hh+lh+hl.
// CTA 128x128, BK=32, 256 threads (8 warps, 32m x 64n).
// 3-stage cp.async pipeline, ONE __syncthreads per K-step:
//   wait(tile kc) -> sync -> issue tile kc+2 -> compute tile kc
// ---------------------------------------------------------------------------
#define GSTAGE 32768
#define GSMEM  (3 * GSTAGE)
#define NCHUNK 32

__device__ __forceinline__ void load_chunk(
    uint32_t sbase, int tid, int m0, int n0, int kc,
    const __nv_bfloat16* __restrict__ Ahi, const __nv_bfloat16* __restrict__ Alo,
    const __nv_bfloat16* __restrict__ Bhi, const __nv_bfloat16* __restrict__ Blo)
{
    const int row = tid >> 2;
    const int chunk = tid & 3;
    const int kcol = kc * 32 + chunk * 8;
#pragma unroll
    for (int u = 0; u < 2; u++) {
        const int r = row + u * 64;
        const uint32_t so = (uint32_t)(r * 64 + ((chunk ^ ((r >> 1) & 3)) << 4));
        CP16(sbase + so,         (const char*)(Ahi + (size_t)(m0 + r) * 1024 + kcol));
        CP16(sbase + 8192 + so,  (const char*)(Alo + (size_t)(m0 + r) * 1024 + kcol));
        CP16(sbase + 16384 + so, (const char*)(Bhi + (size_t)(n0 + r) * 1024 + kcol));
        CP16(sbase + 24576 + so, (const char*)(Blo + (size_t)(n0 + r) * 1024 + kcol));
    }
}

__device__ __forceinline__ void gemm_core(
    uint32_t sb, int tid, int m0, int n0,
    const __nv_bfloat16* __restrict__ Ahi, const __nv_bfloat16* __restrict__ Alo,
    const __nv_bfloat16* __restrict__ Bhi, const __nv_bfloat16* __restrict__ Blo,
    float acc[2][8][4])
{
    const int wid = tid >> 5;
    const int lid = tid & 31;
    const int warp_m = (wid >> 1) * 32;
    const int warp_n = (wid & 1) * 64;
    const int sub = lid >> 3;
    const int r8  = lid & 7;

    load_chunk(sb, tid, m0, n0, 0, Ahi, Alo, Bhi, Blo);
    CP_COMMIT();
    load_chunk(sb + GSTAGE, tid, m0, n0, 1, Ahi, Alo, Bhi, Blo);
    CP_COMMIT();

    uint32_t stage = 0;         // kc % 3
    for (int kc = 0; kc < NCHUNK; kc++) {
        if (kc + 1 < NCHUNK) { CP_WAIT(1); } else { CP_WAIT(0); }
        __syncthreads();
        if (kc + 2 < NCHUNK) {
            uint32_t s2 = stage + 2; if (s2 >= 3) s2 -= 3;
            load_chunk(sb + s2 * GSTAGE, tid, m0, n0, kc + 2, Ahi, Alo, Bhi, Blo);
            CP_COMMIT();
        }
        const uint32_t cur = sb + stage * GSTAGE;
        if (++stage == 3) stage = 0;

#pragma unroll
        for (int ks = 0; ks < 2; ks++) {
            const int kchunk = ks * 2 + (sub >> 1);
            uint32_t ahi[2][4], alo[2][4], bfr[4][4];
            uint32_t bad[4];
#pragma unroll
            for (int mt = 0; mt < 2; mt++) {
                const int mr = warp_m + mt * 16 + ((sub & 1) << 3) + r8;
                const uint32_t ad = cur + (uint32_t)(mr * 64 + ((kchunk ^ ((mr >> 1) & 3)) << 4));
                LDMX4(ahi[mt], ad);
                LDMX4(alo[mt], ad + 8192);
            }
#pragma unroll
            for (int nt = 0; nt < 4; nt++) {
                const int nr = warp_n + nt * 16 + ((sub & 1) << 3) + r8;
                bad[nt] = cur + 16384 + (uint32_t)(nr * 64 + ((kchunk ^ ((nr >> 1) & 3)) << 4));
                LDMX4(bfr[nt], bad[nt]);
            }
#pragma unroll
            for (int mt = 0; mt < 2; mt++)
#pragma unroll
                for (int nt = 0; nt < 4; nt++) {
                    MMA_BF16(acc[mt][2 * nt + 0], ahi[mt], bfr[nt][0], bfr[nt][2]);
                    MMA_BF16(acc[mt][2 * nt + 1], ahi[mt], bfr[nt][1], bfr[nt][3]);
                    MMA_BF16(acc[mt][2 * nt + 0], alo[mt], bfr[nt][0], bfr[nt][2]);
                    MMA_BF16(acc[mt][2 * nt + 1], alo[mt], bfr[nt][1], bfr[nt][3]);
                }
#pragma unroll
            for (int nt = 0; nt < 4; nt++)
                LDMX4(bfr[nt], bad[nt] + 8192);
#pragma unroll
            for (int mt = 0; mt < 2; mt++)
#pragma unroll
                for (int nt = 0; nt < 4; nt++) {
                    MMA_BF16(acc[mt][2 * nt + 0], ahi[mt], bfr[nt][0], bfr[nt][2]);
                    MMA_BF16(acc[mt][2 * nt + 1], ahi[mt], bfr[nt][1], bfr[nt][3]);
                }
        }
    }
}

// Fused QKV projection: grid (24, 32); blockIdx.x -> {sel, n-block}.
// Q output pre-scaled by 0.125*log2(e). K lo-residual never consumed -> skipped.
__global__ __launch_bounds__(256) void gemm_qkv_kernel()
{
    extern __shared__ __align__(128) char smem[];
    const uint32_t sb = smem_u32(smem);
    const int tid = threadIdx.x;
    const int sel = blockIdx.x >> 3;
    const int n0 = (blockIdx.x & 7) * 128;
    const int m0 = blockIdx.y * 128;
    const size_t NW = (size_t)D_MODEL * D_MODEL;

    const __nv_bfloat16* Bhi = &g_whi[0][0] + sel * NW;
    const __nv_bfloat16* Blo = &g_wlo[0][0] + sel * NW;
    __nv_bfloat16* Chi = (sel == 0) ? g_qhi : (sel == 1) ? g_khi : g_vhi;
    __nv_bfloat16* Clo = (sel == 0) ? g_qlo : (sel == 1) ? g_klo : g_vlo;
    const float scale = (sel == 0) ? Q_PRESCALE : 1.0f;
    const bool wlo = (sel != 1);

    float acc[2][8][4];
#pragma unroll
    for (int a = 0; a < 2; a++)
#pragma unroll
        for (int b = 0; b < 8; b++)
#pragma unroll
            for (int c = 0; c < 4; c++) acc[a][b][c] = 0.f;

    gemm_core(sb, tid, m0, n0, g_xhi, g_xlo, Bhi, Blo, acc);

    const int wid = tid >> 5, lid = tid & 31;
    const int warp_m = (wid >> 1) * 32, warp_n = (wid & 1) * 64;
#pragma unroll
    for (int mt = 0; mt < 2; mt++) {
        const int mrow = m0 + warp_m + mt * 16 + (lid >> 2);
#pragma unroll
        for (int nt = 0; nt < 8; nt++) {
            const int ncol = n0 + warp_n + nt * 8 + 2 * (lid & 3);
            const float a0 = acc[mt][nt][0] * scale, a1 = acc[mt][nt][1] * scale;
            const float a2 = acc[mt][nt][2] * scale, a3 = acc[mt][nt][3] * scale;
            *(uint32_t*)(Chi + (size_t)mrow * 1024 + ncol) = pack_bf2(a0, a1);
            *(uint32_t*)(Chi + (size_t)(mrow + 8) * 1024 + ncol) = pack_bf2(a2, a3);
            if (wlo) {
                *(uint32_t*)(Clo + (size_t)mrow * 1024 + ncol) = pack_bf2(bfres(a0), bfres(a1));
                *(uint32_t*)(Clo + (size_t)(mrow + 8) * 1024 + ncol) = pack_bf2(bfres(a2), bfres(a3));
            }
        }
    }
}

// Output projection: fp32 out + bias.
__global__ __launch_bounds__(256) void gemm_out_kernel(
    const float* __restrict__ bias, float* __restrict__ C)
{
    extern __shared__ __align__(128) char smem[];
    const uint32_t sb = smem_u32(smem);
    const int tid = threadIdx.x;
    const int n0 = blockIdx.x * 128;
    const int m0 = blockIdx.y * 128;
    const size_t NW = (size_t)D_MODEL * D_MODEL;

    float acc[2][8][4];
#pragma unroll
    for (int a = 0; a < 2; a++)
#pragma unroll
        for (int b = 0; b < 8; b++)
#pragma unroll
            for (int c = 0; c < 4; c++) acc[a][b][c] = 0.f;

    gemm_core(sb, tid, m0, n0, g_chi, g_clo, &g_whi[0][0] + 3 * NW, &g_wlo[0][0] + 3 * NW, acc);

    const int wid = tid >> 5, lid = tid & 31;
    const int warp_m = (wid >> 1) * 32, warp_n = (wid & 1) * 64;
#pragma unroll
    for (int mt = 0; mt < 2; mt++) {
        const int mrow = m0 + warp_m + mt * 16 + (lid >> 2);
#pragma unroll
        for (int nt = 0; nt < 8; nt++) {
            const int ncol = n0 + warp_n + nt * 8 + 2 * (lid & 3);
            const float b0 = bias[ncol], b1 = bias[ncol + 1];
            *(float2*)(C + (size_t)mrow * 1024 + ncol) =
                make_float2(acc[mt][nt][0] + b0, acc[mt][nt][1] + b1);
            *(float2*)(C + (size_t)(mrow + 8) * 1024 + ncol) =
                make_float2(acc[mt][nt][2] + b0, acc[mt][nt][3] + b1);
        }
    }
}

// ---------------------------------------------------------------------------
// Tensor-core flash attention (causal). CTA processes TWO q-blocks {63-p, p}
// (constant 65 K-tiles per CTA). 128 threads, launch_bounds(128,3).
// QK^T: 2-pass ((Qhi+Qlo)*Khi). PV: 3-pass. exp2 softmax (Q pre-scaled).
// 3-stage cp.async pipeline with compact 24KB stages (Khi|Vhi|Vlo), ONE
// __syncthreads per tile:  wait(tile kb) -> sync -> issue kb+2 -> compute kb.
// Q is staged in the stage-1 region and consumed before stage-1's first load.
// SMEM = 3 x 24KB = 72KB -> 3 CTAs/SM.
// ---------------------------------------------------------------------------
#define A_STSZ 24576
#define A_VHI  8192
#define A_VLO  16384
#define A_SMEM (3 * A_STSZ)   // 73728

__device__ __forceinline__ uint32_t aphys(int row, int chunk) {
    return (uint32_t)(row * 128 + (((chunk) ^ (row & 7)) << 4));
}

__device__ __forceinline__ void attn_load_kv(uint32_t st, int kb, int h, int tid) {
    const int r0 = tid >> 3;
    const int c  = tid & 7;
#pragma unroll
    for (int u = 0; u < 4; u++) {
        const int r = r0 + u * 16;
        const uint32_t so = aphys(r, c);
        const size_t gi = (size_t)(kb * 64 + r) * 1024 + h * 64 + c * 8;
        CP16(st + so,          (const char*)(g_khi + gi));
        CP16(st + A_VHI + so,  (const char*)(g_vhi + gi));
        CP16(st + A_VLO + so,  (const char*)(g_vlo + gi));
    }
}

__global__ __launch_bounds__(128, 3) void attn_kernel()
{
    extern __shared__ __align__(128) char smem[];
    const uint32_t sb = smem_u32(smem);
    const int tid = threadIdx.x;
    const int w = tid >> 5;
    const int l = tid & 31;
    const int p = blockIdx.x;           // 0..31 (pair index)
    const int h = blockIdx.y;

#pragma unroll 1
    for (int half = 0; half < 2; half++) {
        const int qb = half ? p : (63 - p);   // long block first
        const int q0 = qb * 64;
        const int nkt = qb + 1;

        // Prologue: Q (hi+lo) into stage-1 region + KV tile 0 into stage-0.
        {
            const int r0 = tid >> 3;
            const int c  = tid & 7;
#pragma unroll
            for (int u = 0; u < 4; u++) {
                const int r = r0 + u * 16;
                const uint32_t so = aphys(r, c);
                const size_t gi = (size_t)(q0 + r) * 1024 + h * 64 + c * 8;
                CP16(sb + A_STSZ + so,        (const char*)(g_qhi + gi));
                CP16(sb + A_STSZ + 8192 + so, (const char*)(g_qlo + gi));
            }
        }
        attn_load_kv(sb, 0, h, tid);
        CP_COMMIT();
        CP_WAIT(0);
        __syncthreads();

        // Consume Q into register fragments, then free the stage-1 region.
        uint32_t qfh[4][4], qfl[4][4];
        {
            const int row = 16 * w + (l & 15);
#pragma unroll
            for (int ks = 0; ks < 4; ks++) {
                const uint32_t ad = sb + A_STSZ + aphys(row, 2 * ks + (l >> 4));
                LDMX4(qfh[ks], ad);
                LDMX4(qfl[ks], ad + 8192);
            }
        }
        __syncthreads();

        // Prime the pipeline with tile 1 (tile 2 is issued inside iter 0).
        if (1 < nkt) { attn_load_kv(sb + A_STSZ, 1, h, tid); CP_COMMIT(); }

        float O[8][4];
        float m0 = -INFINITY, m1 = -INFINITY, l0 = 0.f, l1 = 0.f;
#pragma unroll
        for (int nt = 0; nt < 8; nt++)
#pragma unroll
            for (int j = 0; j < 4; j++) O[nt][j] = 0.f;

        uint32_t stage = 0;     // kb % 3
        for (int kb = 0; kb < nkt; kb++) {
            if (kb > 0) {
                if (kb + 1 < nkt) { CP_WAIT(1); } else { CP_WAIT(0); }
                __syncthreads();
            }
            if (kb + 2 < nkt) {
                uint32_t s2 = stage + 2; if (s2 >= 3) s2 -= 3;
                attn_load_kv(sb + s2 * A_STSZ, kb + 2, h, tid);
                CP_COMMIT();
            }
            const uint32_t st = sb + stage * A_STSZ;
            if (++stage == 3) stage = 0;

            // ---- S = Q K^T (2-pass: (Qhi+Qlo) * Khi) ----
            float s[8][4];
#pragma unroll
            for (int nt = 0; nt < 8; nt++)
#pragma unroll
                for (int j = 0; j < 4; j++) s[nt][j] = 0.f;

#pragma unroll
            for (int ks = 0; ks < 4; ks++) {
#pragma unroll
                for (int ntp = 0; ntp < 4; ntp++) {
                    const int nrow = ntp * 16 + (l & 15);
                    const uint32_t ad = st + aphys(nrow, 2 * ks + (l >> 4));
                    uint32_t bh[4];
                    LDMX4(bh, ad);
                    MMA_BF16(s[2 * ntp + 0], qfh[ks], bh[0], bh[2]);
                    MMA_BF16(s[2 * ntp + 1], qfh[ks], bh[1], bh[3]);
                    MMA_BF16(s[2 * ntp + 0], qfl[ks], bh[0], bh[2]);
                    MMA_BF16(s[2 * ntp + 1], qfl[ks], bh[1], bh[3]);
                }
            }

            // ---- causal mask (diagonal tile only) ----
            if (kb == qb) {
                const int rl0 = 16 * w + (l >> 2);
#pragma unroll
                for (int nt = 0; nt < 8; nt++) {
                    const int c0 = nt * 8 + 2 * (l & 3);
                    if (c0     > rl0    ) s[nt][0] = -INFINITY;
                    if (c0 + 1 > rl0    ) s[nt][1] = -INFINITY;
                    if (c0     > rl0 + 8) s[nt][2] = -INFINITY;
                    if (c0 + 1 > rl0 + 8) s[nt][3] = -INFINITY;
                }
            }

            // ---- online softmax in base-2 (rows l>>2 and l>>2 + 8) ----
            float mr0 = -INFINITY, mr1 = -INFINITY;
#pragma unroll
            for (int nt = 0; nt < 8; nt++) {
                mr0 = fmaxf(mr0, fmaxf(s[nt][0], s[nt][1]));
                mr1 = fmaxf(mr1, fmaxf(s[nt][2], s[nt][3]));
            }
            mr0 = fmaxf(mr0, __shfl_xor_sync(0xffffffffu, mr0, 1));
            mr0 = fmaxf(mr0, __shfl_xor_sync(0xffffffffu, mr0, 2));
            mr1 = fmaxf(mr1, __shfl_xor_sync(0xffffffffu, mr1, 1));
            mr1 = fmaxf(mr1, __shfl_xor_sync(0xffffffffu, mr1, 2));
            const float mn0 = fmaxf(m0, mr0);
            const float mn1 = fmaxf(m1, mr1);
            const float a0 = exp2f(m0 - mn0);
            const float a1 = exp2f(m1 - mn1);

            float sum0 = 0.f, sum1 = 0.f;
#pragma unroll
            for (int nt = 0; nt < 8; nt++) {
                s[nt][0] = exp2f(s[nt][0] - mn0); sum0 += s[nt][0];
                s[nt][1] = exp2f(s[nt][1] - mn0); sum0 += s[nt][1];
                s[nt][2] = exp2f(s[nt][2] - mn1); sum1 += s[nt][2];
                s[nt][3] = exp2f(s[nt][3] - mn1); sum1 += s[nt][3];
            }
            sum0 += __shfl_xor_sync(0xffffffffu, sum0, 1);
            sum0 += __shfl_xor_sync(0xffffffffu, sum0, 2);
            sum1 += __shfl_xor_sync(0xffffffffu, sum1, 1);
            sum1 += __shfl_xor_sync(0xffffffffu, sum1, 2);
            l0 = l0 * a0 + sum0;
            l1 = l1 * a1 + sum1;
            m0 = mn0; m1 = mn1;

#pragma unroll
            for (int nt = 0; nt < 8; nt++) {
                O[nt][0] *= a0; O[nt][1] *= a0;
                O[nt][2] *= a1; O[nt][3] *= a1;
            }

            // ---- O += P V (3-pass), P packed from registers ----
#pragma unroll
            for (int ks = 0; ks < 4; ks++) {
                uint32_t ph[4], pl[4];
                ph[0] = pack_bf2(s[2 * ks][0],     s[2 * ks][1]);
                ph[1] = pack_bf2(s[2 * ks][2],     s[2 * ks][3]);
                ph[2] = pack_bf2(s[2 * ks + 1][0], s[2 * ks + 1][1]);
                ph[3] = pack_bf2(s[2 * ks + 1][2], s[2 * ks + 1][3]);
                pl[0] = pack_bf2(bfres(s[2 * ks][0]),     bfres(s[2 * ks][1]));
                pl[1] = pack_bf2(bfres(s[2 * ks][2]),     bfres(s[2 * ks][3]));
                pl[2] = pack_bf2(bfres(s[2 * ks + 1][0]), bfres(s[2 * ks + 1][1]));
                pl[3] = pack_bf2(bfres(s[2 * ks + 1][2]), bfres(s[2 * ks + 1][3]));
                const int vrow = 16 * ks + (l & 15);
#pragma unroll
                for (int dtp = 0; dtp < 4; dtp++) {
                    const uint32_t ad = st + A_VHI + aphys(vrow, 2 * dtp + (l >> 4));
                    uint32_t vh[4], vl[4];
                    LDMX4T(vh, ad);
                    LDMX4T(vl, ad + 8192);
                    MMA_BF16(O[2 * dtp + 0], ph, vh[0], vh[1]);
                    MMA_BF16(O[2 * dtp + 1], ph, vh[2], vh[3]);
                    MMA_BF16(O[2 * dtp + 0], pl, vh[0], vh[1]);
                    MMA_BF16(O[2 * dtp + 1], pl, vh[2], vh[3]);
                    MMA_BF16(O[2 * dtp + 0], ph, vl[0], vl[1]);
                    MMA_BF16(O[2 * dtp + 1], ph, vl[2], vl[3]);
                }
            }
        }

        // ---- epilogue: ctx hi/lo bf16 ----
        const float i0 = 1.f / l0;
        const float i1 = 1.f / l1;
        const int rg0 = q0 + 16 * w + (l >> 2);
        const int cb = h * 64 + 2 * (l & 3);
#pragma unroll
        for (int nt = 0; nt < 8; nt++) {
            const float v00 = O[nt][0] * i0, v01 = O[nt][1] * i0;
            const float v10 = O[nt][2] * i1, v11 = O[nt][3] * i1;
            const size_t o0 = (size_t)rg0 * 1024 + cb + nt * 8;
            const size_t o1 = (size_t)(rg0 + 8) * 1024 + cb + nt * 8;
            *(uint32_t*)(g_chi + o0) = pack_bf2(v00, v01);
            *(uint32_t*)(g_clo + o0) = pack_bf2(bfres(v00), bfres(v01));
            *(uint32_t*)(g_chi + o1) = pack_bf2(v10, v11);
            *(uint32_t*)(g_clo + o1) = pack_bf2(bfres(v10), bfres(v11));
        }
        // Barrier between halves: all warps must finish reading the last KV
        // stage before the next half's prologue overwrites stages 0/1.
        __syncthreads();
    }
}

// ---------------------------------------------------------------------------
extern "C" void kernel_launch(void* const* d_in, const int* in_sizes, int n_in,
                              void* d_out, int out_size)
{
    const float* x  = (const float*)d_in[0];
    const float* Wq = (const float*)d_in[1];
    const float* Wk = (const float*)d_in[2];
    const float* Wv = (const float*)d_in[3];
    const float* Wo = (const float*)d_in[4];
    const float* bo = (const float*)d_in[5];
    float* out = (float*)d_out;

    __nv_bfloat16 *xhi, *xlo;
    cudaGetSymbolAddress((void**)&xhi, g_xhi);
    cudaGetSymbolAddress((void**)&xlo, g_xlo);

    const int NX = N_TOK * D_MODEL;       // 4M
    const int NW = D_MODEL * D_MODEL;     // 1M

    split_kernel<<<NX / 1024, 256>>>(x, xhi, xlo, NX);
    split_w_kernel<<<dim3(NW / 1024, 4), 256>>>(Wq, Wk, Wv, Wo);

    cudaFuncSetAttribute(gemm_qkv_kernel, cudaFuncAttributeMaxDynamicSharedMemorySize, GSMEM);
    cudaFuncSetAttribute(gemm_out_kernel, cudaFuncAttributeMaxDynamicSharedMemorySize, GSMEM);

    gemm_qkv_kernel<<<dim3(24, 32), 256, GSMEM>>>();

    cudaFuncSetAttribute(attn_kernel, cudaFuncAttributeMaxDynamicSharedMemorySize, A_SMEM);
    attn_kernel<<<dim3(32, N_HEADS), 128, A_SMEM>>>();

    gemm_out_kernel<<<dim3(8, 32), 256, GSMEM>>>(bo, out);
}

// round 12
// speedup vs baseline: 1.0128x; 1.0128x over previous
#include <cuda_runtime.h>
#include <cuda_bf16.h>
#include <math.h>
#include <stdint.h>

#define N_TOK   4096
#define D_MODEL 1024
#define N_HEADS 16
#define HEAD_DIM 64

// 0.125 * log2(e): folded into Q at projection time so attention can use exp2.
#define Q_PRESCALE 0.18033688011112042f

// ---------------- device scratch (allocation-free rule) ----------------
__device__ __nv_bfloat16 g_xhi[N_TOK * D_MODEL];
__device__ __nv_bfloat16 g_xlo[N_TOK * D_MODEL];
__device__ __nv_bfloat16 g_whi[4][D_MODEL * D_MODEL];
__device__ __nv_bfloat16 g_wlo[4][D_MODEL * D_MODEL];
__device__ __nv_bfloat16 g_qhi[N_TOK * D_MODEL];
__device__ __nv_bfloat16 g_qlo[N_TOK * D_MODEL];
__device__ __nv_bfloat16 g_khi[N_TOK * D_MODEL];
__device__ __nv_bfloat16 g_klo[N_TOK * D_MODEL];   // dead (2-pass QK^T); kept for layout
__device__ __nv_bfloat16 g_vhi[N_TOK * D_MODEL];
__device__ __nv_bfloat16 g_vlo[N_TOK * D_MODEL];
__device__ __nv_bfloat16 g_chi[N_TOK * D_MODEL];
__device__ __nv_bfloat16 g_clo[N_TOK * D_MODEL];

// ---------------- PTX helpers (sm_80-compatible; NO tcgen05) ------------
__device__ __forceinline__ uint32_t smem_u32(const void* p) {
    uint32_t a;
    asm("{ .reg .u64 t; cvta.to.shared.u64 t, %1; cvt.u32.u64 %0, t; }" : "=r"(a) : "l"(p));
    return a;
}

#define CP16(s, g) \
    asm volatile("cp.async.cg.shared.global [%0], [%1], 16;" :: "r"(s), "l"(g))
#define CP_COMMIT() asm volatile("cp.async.commit_group;" ::: "memory")
#define CP_WAIT(n)  asm volatile("cp.async.wait_group %0;" :: "n"(n) : "memory")

#define LDMX4(r, addr) \
    asm volatile("ldmatrix.sync.aligned.m8n8.x4.shared.b16 {%0,%1,%2,%3}, [%4];" \
        : "=r"((r)[0]), "=r"((r)[1]), "=r"((r)[2]), "=r"((r)[3]) : "r"(addr))

#define LDMX4T(r, addr) \
    asm volatile("ldmatrix.sync.aligned.m8n8.x4.trans.shared.b16 {%0,%1,%2,%3}, [%4];" \
        : "=r"((r)[0]), "=r"((r)[1]), "=r"((r)[2]), "=r"((r)[3]) : "r"(addr))

#define MMA_BF16(d, a, b0, b1) \
    asm volatile("mma.sync.aligned.m16n8k16.row.col.f32.bf16.bf16.f32 " \
        "{%0,%1,%2,%3}, {%4,%5,%6,%7}, {%8,%9}, {%0,%1,%2,%3};" \
        : "+f"((d)[0]), "+f"((d)[1]), "+f"((d)[2]), "+f"((d)[3]) \
        : "r"((a)[0]), "r"((a)[1]), "r"((a)[2]), "r"((a)[3]), "r"(b0), "r"(b1))

__device__ __forceinline__ uint32_t pack_bf2(float a, float b) {
    uint32_t r;
    asm("cvt.rn.bf16x2.f32 %0, %1, %2;" : "=r"(r) : "f"(b), "f"(a));
    return r;
}
// Residual pair from the already-packed hi pair (no F2FP round-trip):
// low half of ph is bf16(a), high half is bf16(b).
__device__ __forceinline__ uint32_t pack_res2(float a, float b, uint32_t ph) {
    const float ra = a - __uint_as_float(ph << 16);
    const float rb = b - __uint_as_float(ph & 0xFFFF0000u);
    return pack_bf2(ra, rb);
}
// Guaranteed-MUFU exp2 / rcp (exp2f/1.f/x may lower to slow accurate paths).
__device__ __forceinline__ float ex2(float x) {
    float r; asm("ex2.approx.f32 %0, %1;" : "=f"(r) : "f"(x)); return r;
}
__device__ __forceinline__ float rcp(float x) {
    float r; asm("rcp.approx.f32 %0, %1;" : "=f"(r) : "f"(x)); return r;
}

// ---------------------------------------------------------------------------
// split fp32 -> bf16 hi + bf16 lo. x variant + fused 4-weight variant.
// ---------------------------------------------------------------------------
__global__ __launch_bounds__(256) void split_kernel(
    const float* __restrict__ src, __nv_bfloat16* __restrict__ hi,
    __nv_bfloat16* __restrict__ lo, int n)
{
    int i = (blockIdx.x * 256 + threadIdx.x) * 4;
    if (i >= n) return;
    float4 v = *(const float4*)(src + i);
    uint32_t* ph = (uint32_t*)(hi + i);
    uint32_t* pl = (uint32_t*)(lo + i);
    uint32_t h0 = pack_bf2(v.x, v.y), h1 = pack_bf2(v.z, v.w);
    ph[0] = h0; ph[1] = h1;
    pl[0] = pack_res2(v.x, v.y, h0);
    pl[1] = pack_res2(v.z, v.w, h1);
}

__global__ __launch_bounds__(256) void split_w_kernel(
    const float* __restrict__ w0, const float* __restrict__ w1,
    const float* __restrict__ w2, const float* __restrict__ w3)
{
    const int sel = blockIdx.y;
    const float* src = (sel == 0) ? w0 : (sel == 1) ? w1 : (sel == 2) ? w2 : w3;
    const size_t NW = (size_t)D_MODEL * D_MODEL;
    __nv_bfloat16* hi = &g_whi[0][0] + sel * NW;
    __nv_bfloat16* lo = &g_wlo[0][0] + sel * NW;
    int i = (blockIdx.x * 256 + threadIdx.x) * 4;
    float4 v = *(const float4*)(src + i);
    uint32_t* ph = (uint32_t*)(hi + i);
    uint32_t* pl = (uint32_t*)(lo + i);
    uint32_t h0 = pack_bf2(v.x, v.y), h1 = pack_bf2(v.z, v.w);
    ph[0] = h0; ph[1] = h1;
    pl[0] = pack_res2(v.x, v.y, h0);
    pl[1] = pack_res2(v.z, v.w, h1);
}

// ---------------------------------------------------------------------------
// Shared HMMA split-bf16 GEMM core: acc += A[m][k]*B[n][k], 3-pass hh+lh+hl.
// CTA 128x128, BK=32, 256 threads (8 warps, 32m x 64n).
// 2-stage cp.async pipeline, ONE __syncthreads per K-step:
//   wait(tile kc) -> sync -> issue tile kc+1 -> compute tile kc
// ---------------------------------------------------------------------------
#define GSTAGE 32768
#define GSMEM  (2 * GSTAGE)
#define NCHUNK 32

__device__ __forceinline__ void load_chunk(
    uint32_t sbase, int tid, int m0, int n0, int kc,
    const __nv_bfloat16* __restrict__ Ahi, const __nv_bfloat16* __restrict__ Alo,
    const __nv_bfloat16* __restrict__ Bhi, const __nv_bfloat16* __restrict__ Blo)
{
    const int row = tid >> 2;
    const int chunk = tid & 3;
    const int kcol = kc * 32 + chunk * 8;
#pragma unroll
    for (int u = 0; u < 2; u++) {
        const int r = row + u * 64;
        const uint32_t so = (uint32_t)(r * 64 + ((chunk ^ ((r >> 1) & 3)) << 4));
        CP16(sbase + so,         (const char*)(Ahi + (size_t)(m0 + r) * 1024 + kcol));
        CP16(sbase + 8192 + so,  (const char*)(Alo + (size_t)(m0 + r) * 1024 + kcol));
        CP16(sbase + 16384 + so, (const char*)(Bhi + (size_t)(n0 + r) * 1024 + kcol));
        CP16(sbase + 24576 + so, (const char*)(Blo + (size_t)(n0 + r) * 1024 + kcol));
    }
}

__device__ __forceinline__ void gemm_core(
    uint32_t sb, int tid, int m0, int n0,
    const __nv_bfloat16* __restrict__ Ahi, const __nv_bfloat16* __restrict__ Alo,
    const __nv_bfloat16* __restrict__ Bhi, const __nv_bfloat16* __restrict__ Blo,
    float acc[2][8][4])
{
    const int wid = tid >> 5;
    const int lid = tid & 31;
    const int warp_m = (wid >> 1) * 32;
    const int warp_n = (wid & 1) * 64;
    const int sub = lid >> 3;
    const int r8  = lid & 7;

    load_chunk(sb, tid, m0, n0, 0, Ahi, Alo, Bhi, Blo);
    CP_COMMIT();

    for (int kc = 0; kc < NCHUNK; kc++) {
        CP_WAIT(0);                 // chunk kc complete (only group in flight)
        __syncthreads();            // publish kc; buffer (kc+1)&1 fully consumed
        if (kc + 1 < NCHUNK) {
            load_chunk(sb + (uint32_t)((kc + 1) & 1) * GSTAGE, tid, m0, n0, kc + 1,
                       Ahi, Alo, Bhi, Blo);
            CP_COMMIT();
        }
        const uint32_t cur = sb + (uint32_t)(kc & 1) * GSTAGE;

#pragma unroll
        for (int ks = 0; ks < 2; ks++) {
            const int kchunk = ks * 2 + (sub >> 1);
            uint32_t ahi[2][4], alo[2][4], bfr[4][4];
            uint32_t bad[4];
#pragma unroll
            for (int mt = 0; mt < 2; mt++) {
                const int mr = warp_m + mt * 16 + ((sub & 1) << 3) + r8;
                const uint32_t ad = cur + (uint32_t)(mr * 64 + ((kchunk ^ ((mr >> 1) & 3)) << 4));
                LDMX4(ahi[mt], ad);
                LDMX4(alo[mt], ad + 8192);
            }
#pragma unroll
            for (int nt = 0; nt < 4; nt++) {
                const int nr = warp_n + nt * 16 + ((sub & 1) << 3) + r8;
                bad[nt] = cur + 16384 + (uint32_t)(nr * 64 + ((kchunk ^ ((nr >> 1) & 3)) << 4));
                LDMX4(bfr[nt], bad[nt]);
            }
#pragma unroll
            for (int mt = 0; mt < 2; mt++)
#pragma unroll
                for (int nt = 0; nt < 4; nt++) {
                    MMA_BF16(acc[mt][2 * nt + 0], ahi[mt], bfr[nt][0], bfr[nt][2]);
                    MMA_BF16(acc[mt][2 * nt + 1], ahi[mt], bfr[nt][1], bfr[nt][3]);
                    MMA_BF16(acc[mt][2 * nt + 0], alo[mt], bfr[nt][0], bfr[nt][2]);
                    MMA_BF16(acc[mt][2 * nt + 1], alo[mt], bfr[nt][1], bfr[nt][3]);
                }
#pragma unroll
            for (int nt = 0; nt < 4; nt++)
                LDMX4(bfr[nt], bad[nt] + 8192);
#pragma unroll
            for (int mt = 0; mt < 2; mt++)
#pragma unroll
                for (int nt = 0; nt < 4; nt++) {
                    MMA_BF16(acc[mt][2 * nt + 0], ahi[mt], bfr[nt][0], bfr[nt][2]);
                    MMA_BF16(acc[mt][2 * nt + 1], ahi[mt], bfr[nt][1], bfr[nt][3]);
                }
        }
    }
}

// Fused QKV projection: grid (24, 32); blockIdx.x -> {sel, n-block}.
// Q output pre-scaled by 0.125*log2(e). K lo-residual never consumed -> skipped.
__global__ __launch_bounds__(256) void gemm_qkv_kernel()
{
    extern __shared__ __align__(128) char smem[];
    const uint32_t sb = smem_u32(smem);
    const int tid = threadIdx.x;
    const int sel = blockIdx.x >> 3;
    const int n0 = (blockIdx.x & 7) * 128;
    const int m0 = blockIdx.y * 128;
    const size_t NW = (size_t)D_MODEL * D_MODEL;

    const __nv_bfloat16* Bhi = &g_whi[0][0] + sel * NW;
    const __nv_bfloat16* Blo = &g_wlo[0][0] + sel * NW;
    __nv_bfloat16* Chi = (sel == 0) ? g_qhi : (sel == 1) ? g_khi : g_vhi;
    __nv_bfloat16* Clo = (sel == 0) ? g_qlo : (sel == 1) ? g_klo : g_vlo;
    const float scale = (sel == 0) ? Q_PRESCALE : 1.0f;
    const bool wlo = (sel != 1);

    float acc[2][8][4];
#pragma unroll
    for (int a = 0; a < 2; a++)
#pragma unroll
        for (int b = 0; b < 8; b++)
#pragma unroll
            for (int c = 0; c < 4; c++) acc[a][b][c] = 0.f;

    gemm_core(sb, tid, m0, n0, g_xhi, g_xlo, Bhi, Blo, acc);

    const int wid = tid >> 5, lid = tid & 31;
    const int warp_m = (wid >> 1) * 32, warp_n = (wid & 1) * 64;
#pragma unroll
    for (int mt = 0; mt < 2; mt++) {
        const int mrow = m0 + warp_m + mt * 16 + (lid >> 2);
#pragma unroll
        for (int nt = 0; nt < 8; nt++) {
            const int ncol = n0 + warp_n + nt * 8 + 2 * (lid & 3);
            const float a0 = acc[mt][nt][0] * scale, a1 = acc[mt][nt][1] * scale;
            const float a2 = acc[mt][nt][2] * scale, a3 = acc[mt][nt][3] * scale;
            const uint32_t h0 = pack_bf2(a0, a1), h1 = pack_bf2(a2, a3);
            *(uint32_t*)(Chi + (size_t)mrow * 1024 + ncol) = h0;
            *(uint32_t*)(Chi + (size_t)(mrow + 8) * 1024 + ncol) = h1;
            if (wlo) {
                *(uint32_t*)(Clo + (size_t)mrow * 1024 + ncol) = pack_res2(a0, a1, h0);
                *(uint32_t*)(Clo + (size_t)(mrow + 8) * 1024 + ncol) = pack_res2(a2, a3, h1);
            }
        }
    }
}

// Output projection: fp32 out + bias.
__global__ __launch_bounds__(256) void gemm_out_kernel(
    const float* __restrict__ bias, float* __restrict__ C)
{
    extern __shared__ __align__(128) char smem[];
    const uint32_t sb = smem_u32(smem);
    const int tid = threadIdx.x;
    const int n0 = blockIdx.x * 128;
    const int m0 = blockIdx.y * 128;
    const size_t NW = (size_t)D_MODEL * D_MODEL;

    float acc[2][8][4];
#pragma unroll
    for (int a = 0; a < 2; a++)
#pragma unroll
        for (int b = 0; b < 8; b++)
#pragma unroll
            for (int c = 0; c < 4; c++) acc[a][b][c] = 0.f;

    gemm_core(sb, tid, m0, n0, g_chi, g_clo, &g_whi[0][0] + 3 * NW, &g_wlo[0][0] + 3 * NW, acc);

    const int wid = tid >> 5, lid = tid & 31;
    const int warp_m = (wid >> 1) * 32, warp_n = (wid & 1) * 64;
#pragma unroll
    for (int mt = 0; mt < 2; mt++) {
        const int mrow = m0 + warp_m + mt * 16 + (lid >> 2);
#pragma unroll
        for (int nt = 0; nt < 8; nt++) {
            const int ncol = n0 + warp_n + nt * 8 + 2 * (lid & 3);
            const float b0 = bias[ncol], b1 = bias[ncol + 1];
            *(float2*)(C + (size_t)mrow * 1024 + ncol) =
                make_float2(acc[mt][nt][0] + b0, acc[mt][nt][1] + b1);
            *(float2*)(C + (size_t)(mrow + 8) * 1024 + ncol) =
                make_float2(acc[mt][nt][2] + b0, acc[mt][nt][3] + b1);
        }
    }
}

// ---------------------------------------------------------------------------
// Tensor-core flash attention (causal). CTA processes TWO q-blocks {63-p, p}
// (constant 65 K-tiles per CTA). 128 threads, launch_bounds(128,3).
// QK^T: 2-pass ((Qhi+Qlo)*Khi). PV: 3-pass. MUFU ex2 softmax (Q pre-scaled).
// 2-stage cp.async pipeline with compact 24KB stages (Khi|Vhi|Vlo), ONE
// __syncthreads per tile. Q staged in stage-1, consumed before kv1 lands.
// SMEM = 2 x 24KB = 48KB -> 3 CTAs/SM (regs are the limiter).
// ---------------------------------------------------------------------------
#define A_STSZ 24576
#define A_VHI  8192
#define A_VLO  16384
#define A_SMEM (2 * A_STSZ)   // 49152

__device__ __forceinline__ uint32_t aphys(int row, int chunk) {
    return (uint32_t)(row * 128 + (((chunk) ^ (row & 7)) << 4));
}

__device__ __forceinline__ void attn_load_kv(uint32_t st, int kb, int h, int tid) {
    const int r0 = tid >> 3;
    const int c  = tid & 7;
#pragma unroll
    for (int u = 0; u < 4; u++) {
        const int r = r0 + u * 16;
        const uint32_t so = aphys(r, c);
        const size_t gi = (size_t)(kb * 64 + r) * 1024 + h * 64 + c * 8;
        CP16(st + so,          (const char*)(g_khi + gi));
        CP16(st + A_VHI + so,  (const char*)(g_vhi + gi));
        CP16(st + A_VLO + so,  (const char*)(g_vlo + gi));
    }
}

__global__ __launch_bounds__(128, 3) void attn_kernel()
{
    extern __shared__ __align__(128) char smem[];
    const uint32_t sb = smem_u32(smem);
    const int tid = threadIdx.x;
    const int w = tid >> 5;
    const int l = tid & 31;
    const int p = blockIdx.x;           // 0..31 (pair index)
    const int h = blockIdx.y;

#pragma unroll 1
    for (int half = 0; half < 2; half++) {
        const int qb = half ? p : (63 - p);   // long block first
        const int q0 = qb * 64;
        const int nkt = qb + 1;

        // Prologue: Q (hi+lo) into stage-1 region + KV tile 0 into stage-0.
        {
            const int r0 = tid >> 3;
            const int c  = tid & 7;
#pragma unroll
            for (int u = 0; u < 4; u++) {
                const int r = r0 + u * 16;
                const uint32_t so = aphys(r, c);
                const size_t gi = (size_t)(q0 + r) * 1024 + h * 64 + c * 8;
                CP16(sb + A_STSZ + so,        (const char*)(g_qhi + gi));
                CP16(sb + A_STSZ + 8192 + so, (const char*)(g_qlo + gi));
            }
        }
        attn_load_kv(sb, 0, h, tid);
        CP_COMMIT();
        CP_WAIT(0);
        __syncthreads();

        // Consume Q into register fragments, then free the stage-1 region.
        uint32_t qfh[4][4], qfl[4][4];
        {
            const int row = 16 * w + (l & 15);
#pragma unroll
            for (int ks = 0; ks < 4; ks++) {
                const uint32_t ad = sb + A_STSZ + aphys(row, 2 * ks + (l >> 4));
                LDMX4(qfh[ks], ad);
                LDMX4(qfl[ks], ad + 8192);
            }
        }
        __syncthreads();   // all warps done with Q region; kv loads may overwrite

        float O[8][4];
        float m0 = -INFINITY, m1 = -INFINITY, l0 = 0.f, l1 = 0.f;
#pragma unroll
        for (int nt = 0; nt < 8; nt++)
#pragma unroll
            for (int j = 0; j < 4; j++) O[nt][j] = 0.f;

        for (int kb = 0; kb < nkt; kb++) {
            if (kb > 0) {
                CP_WAIT(0);        // kv kb complete
                __syncthreads();   // publish kb; stage (kb+1)&1 consumed
            }
            if (kb + 1 < nkt) {
                attn_load_kv(sb + (uint32_t)((kb + 1) & 1) * A_STSZ, kb + 1, h, tid);
                CP_COMMIT();
            }
            const uint32_t st = sb + (uint32_t)(kb & 1) * A_STSZ;

            // ---- S = Q K^T (2-pass: (Qhi+Qlo) * Khi) ----
            float s[8][4];
#pragma unroll
            for (int nt = 0; nt < 8; nt++)
#pragma unroll
                for (int j = 0; j < 4; j++) s[nt][j] = 0.f;

#pragma unroll
            for (int ks = 0; ks < 4; ks++) {
#pragma unroll
                for (int ntp = 0; ntp < 4; ntp++) {
                    const int nrow = ntp * 16 + (l & 15);
                    const uint32_t ad = st + aphys(nrow, 2 * ks + (l >> 4));
                    uint32_t bh[4];
                    LDMX4(bh, ad);
                    MMA_BF16(s[2 * ntp + 0], qfh[ks], bh[0], bh[2]);
                    MMA_BF16(s[2 * ntp + 1], qfh[ks], bh[1], bh[3]);
                    MMA_BF16(s[2 * ntp + 0], qfl[ks], bh[0], bh[2]);
                    MMA_BF16(s[2 * ntp + 1], qfl[ks], bh[1], bh[3]);
                }
            }

            // ---- causal mask (diagonal tile only) ----
            if (kb == qb) {
                const int rl0 = 16 * w + (l >> 2);
#pragma unroll
                for (int nt = 0; nt < 8; nt++) {
                    const int c0 = nt * 8 + 2 * (l & 3);
                    if (c0     > rl0    ) s[nt][0] = -INFINITY;
                    if (c0 + 1 > rl0    ) s[nt][1] = -INFINITY;
                    if (c0     > rl0 + 8) s[nt][2] = -INFINITY;
                    if (c0 + 1 > rl0 + 8) s[nt][3] = -INFINITY;
                }
            }

            // ---- online softmax in base-2 (rows l>>2 and l>>2 + 8) ----
            float mr0 = -INFINITY, mr1 = -INFINITY;
#pragma unroll
            for (int nt = 0; nt < 8; nt++) {
                mr0 = fmaxf(mr0, fmaxf(s[nt][0], s[nt][1]));
                mr1 = fmaxf(mr1, fmaxf(s[nt][2], s[nt][3]));
            }
            mr0 = fmaxf(mr0, __shfl_xor_sync(0xffffffffu, mr0, 1));
            mr0 = fmaxf(mr0, __shfl_xor_sync(0xffffffffu, mr0, 2));
            mr1 = fmaxf(mr1, __shfl_xor_sync(0xffffffffu, mr1, 1));
            mr1 = fmaxf(mr1, __shfl_xor_sync(0xffffffffu, mr1, 2));
            const float mn0 = fmaxf(m0, mr0);
            const float mn1 = fmaxf(m1, mr1);
            const float a0 = ex2(m0 - mn0);
            const float a1 = ex2(m1 - mn1);

            float sum0 = 0.f, sum1 = 0.f;
#pragma unroll
            for (int nt = 0; nt < 8; nt++) {
                s[nt][0] = ex2(s[nt][0] - mn0); sum0 += s[nt][0];
                s[nt][1] = ex2(s[nt][1] - mn0); sum0 += s[nt][1];
                s[nt][2] = ex2(s[nt][2] - mn1); sum1 += s[nt][2];
                s[nt][3] = ex2(s[nt][3] - mn1); sum1 += s[nt][3];
            }
            sum0 += __shfl_xor_sync(0xffffffffu, sum0, 1);
            sum0 += __shfl_xor_sync(0xffffffffu, sum0, 2);
            sum1 += __shfl_xor_sync(0xffffffffu, sum1, 1);
            sum1 += __shfl_xor_sync(0xffffffffu, sum1, 2);
            l0 = l0 * a0 + sum0;
            l1 = l1 * a1 + sum1;
            m0 = mn0; m1 = mn1;

#pragma unroll
            for (int nt = 0; nt < 8; nt++) {
                O[nt][0] *= a0; O[nt][1] *= a0;
                O[nt][2] *= a1; O[nt][3] *= a1;
            }

            // ---- O += P V (3-pass), P packed from registers ----
#pragma unroll
            for (int ks = 0; ks < 4; ks++) {
                uint32_t ph[4], pl[4];
                ph[0] = pack_bf2(s[2 * ks][0],     s[2 * ks][1]);
                ph[1] = pack_bf2(s[2 * ks][2],     s[2 * ks][3]);
                ph[2] = pack_bf2(s[2 * ks + 1][0], s[2 * ks + 1][1]);
                ph[3] = pack_bf2(s[2 * ks + 1][2], s[2 * ks + 1][3]);
                pl[0] = pack_res2(s[2 * ks][0],     s[2 * ks][1],     ph[0]);
                pl[1] = pack_res2(s[2 * ks][2],     s[2 * ks][3],     ph[1]);
                pl[2] = pack_res2(s[2 * ks + 1][0], s[2 * ks + 1][1], ph[2]);
                pl[3] = pack_res2(s[2 * ks + 1][2], s[2 * ks + 1][3], ph[3]);
                const int vrow = 16 * ks + (l & 15);
#pragma unroll
                for (int dtp = 0; dtp < 4; dtp++) {
                    const uint32_t ad = st + A_VHI + aphys(vrow, 2 * dtp + (l >> 4));
                    uint32_t vh[4], vl[4];
                    LDMX4T(vh, ad);
                    LDMX4T(vl, ad + 8192);
                    MMA_BF16(O[2 * dtp + 0], ph, vh[0], vh[1]);
                    MMA_BF16(O[2 * dtp + 1], ph, vh[2], vh[3]);
                    MMA_BF16(O[2 * dtp + 0], pl, vh[0], vh[1]);
                    MMA_BF16(O[2 * dtp + 1], pl, vh[2], vh[3]);
                    MMA_BF16(O[2 * dtp + 0], ph, vl[0], vl[1]);
                    MMA_BF16(O[2 * dtp + 1], ph, vl[2], vl[3]);
                }
            }
        }

        // ---- epilogue: ctx hi/lo bf16 ----
        const float i0 = rcp(l0);
        const float i1 = rcp(l1);
        const int rg0 = q0 + 16 * w + (l >> 2);
        const int cb = h * 64 + 2 * (l & 3);
#pragma unroll
        for (int nt = 0; nt < 8; nt++) {
            const float v00 = O[nt][0] * i0, v01 = O[nt][1] * i0;
            const float v10 = O[nt][2] * i1, v11 = O[nt][3] * i1;
            const size_t o0 = (size_t)rg0 * 1024 + cb + nt * 8;
            const size_t o1 = (size_t)(rg0 + 8) * 1024 + cb + nt * 8;
            const uint32_t h0 = pack_bf2(v00, v01), h1 = pack_bf2(v10, v11);
            *(uint32_t*)(g_chi + o0) = h0;
            *(uint32_t*)(g_clo + o0) = pack_res2(v00, v01, h0);
            *(uint32_t*)(g_chi + o1) = h1;
            *(uint32_t*)(g_clo + o1) = pack_res2(v10, v11, h1);
        }
        // Barrier between halves: all warps must finish reading the last KV
        // stage before the next half's prologue overwrites both stages.
        __syncthreads();
    }
}

// ---------------------------------------------------------------------------
extern "C" void kernel_launch(void* const* d_in, const int* in_sizes, int n_in,
                              void* d_out, int out_size)
{
    const float* x  = (const float*)d_in[0];
    const float* Wq = (const float*)d_in[1];
    const float* Wk = (const float*)d_in[2];
    const float* Wv = (const float*)d_in[3];
    const float* Wo = (const float*)d_in[4];
    const float* bo = (const float*)d_in[5];
    float* out = (float*)d_out;

    __nv_bfloat16 *xhi, *xlo;
    cudaGetSymbolAddress((void**)&xhi, g_xhi);
    cudaGetSymbolAddress((void**)&xlo, g_xlo);

    const int NX = N_TOK * D_MODEL;       // 4M
    const int NW = D_MODEL * D_MODEL;     // 1M

    split_kernel<<<NX / 1024, 256>>>(x, xhi, xlo, NX);
    split_w_kernel<<<dim3(NW / 1024, 4), 256>>>(Wq, Wk, Wv, Wo);

    cudaFuncSetAttribute(gemm_qkv_kernel, cudaFuncAttributeMaxDynamicSharedMemorySize, GSMEM);
    cudaFuncSetAttribute(gemm_out_kernel, cudaFuncAttributeMaxDynamicSharedMemorySize, GSMEM);

    gemm_qkv_kernel<<<dim3(24, 32), 256, GSMEM>>>();

    cudaFuncSetAttribute(attn_kernel, cudaFuncAttributeMaxDynamicSharedMemorySize, A_SMEM);
    attn_kernel<<<dim3(32, N_HEADS), 128, A_SMEM>>>();

    gemm_out_kernel<<<dim3(8, 32), 256, GSMEM>>>(bo, out);
}

// round 13
// speedup vs baseline: 1.1788x; 1.1639x over previous
#include <cuda_runtime.h>
#include <cuda_bf16.h>
#include <cuda_fp16.h>
#include <math.h>
#include <stdint.h>

#define N_TOK   4096
#define D_MODEL 1024
#define N_HEADS 16
#define HEAD_DIM 64

// 0.125 * log2(e): folded into Q at projection time so attention can use exp2.
#define Q_PRESCALE 0.18033688011112042f

// ---------------- device scratch (allocation-free rule) ----------------
__device__ __nv_bfloat16 g_xhi[N_TOK * D_MODEL];
__device__ __nv_bfloat16 g_xlo[N_TOK * D_MODEL];
__device__ __nv_bfloat16 g_whi[4][D_MODEL * D_MODEL];
__device__ __nv_bfloat16 g_wlo[4][D_MODEL * D_MODEL];
__device__ __nv_bfloat16 g_qhi[N_TOK * D_MODEL];
__device__ __nv_bfloat16 g_qlo[N_TOK * D_MODEL];
__device__ __nv_bfloat16 g_khi[N_TOK * D_MODEL];
__device__ __half        g_vf[N_TOK * D_MODEL];    // V in fp16 (single)
__device__ __nv_bfloat16 g_chi[N_TOK * D_MODEL];
__device__ __nv_bfloat16 g_clo[N_TOK * D_MODEL];

// ---------------- PTX helpers (sm_80-compatible; NO tcgen05) ------------
__device__ __forceinline__ uint32_t smem_u32(const void* p) {
    uint32_t a;
    asm("{ .reg .u64 t; cvta.to.shared.u64 t, %1; cvt.u32.u64 %0, t; }" : "=r"(a) : "l"(p));
    return a;
}

#define CP16(s, g) \
    asm volatile("cp.async.cg.shared.global [%0], [%1], 16;" :: "r"(s), "l"(g))
#define CP_COMMIT() asm volatile("cp.async.commit_group;" ::: "memory")
#define CP_WAIT(n)  asm volatile("cp.async.wait_group %0;" :: "n"(n) : "memory")

#define LDMX4(r, addr) \
    asm volatile("ldmatrix.sync.aligned.m8n8.x4.shared.b16 {%0,%1,%2,%3}, [%4];" \
        : "=r"((r)[0]), "=r"((r)[1]), "=r"((r)[2]), "=r"((r)[3]) : "r"(addr))

#define LDMX4T(r, addr) \
    asm volatile("ldmatrix.sync.aligned.m8n8.x4.trans.shared.b16 {%0,%1,%2,%3}, [%4];" \
        : "=r"((r)[0]), "=r"((r)[1]), "=r"((r)[2]), "=r"((r)[3]) : "r"(addr))

#define MMA_BF16(d, a, b0, b1) \
    asm volatile("mma.sync.aligned.m16n8k16.row.col.f32.bf16.bf16.f32 " \
        "{%0,%1,%2,%3}, {%4,%5,%6,%7}, {%8,%9}, {%0,%1,%2,%3};" \
        : "+f"((d)[0]), "+f"((d)[1]), "+f"((d)[2]), "+f"((d)[3]) \
        : "r"((a)[0]), "r"((a)[1]), "r"((a)[2]), "r"((a)[3]), "r"(b0), "r"(b1))

#define MMA_F16(d, a, b0, b1) \
    asm volatile("mma.sync.aligned.m16n8k16.row.col.f32.f16.f16.f32 " \
        "{%0,%1,%2,%3}, {%4,%5,%6,%7}, {%8,%9}, {%0,%1,%2,%3};" \
        : "+f"((d)[0]), "+f"((d)[1]), "+f"((d)[2]), "+f"((d)[3]) \
        : "r"((a)[0]), "r"((a)[1]), "r"((a)[2]), "r"((a)[3]), "r"(b0), "r"(b1))

__device__ __forceinline__ uint32_t pack_bf2(float a, float b) {
    uint32_t r;
    asm("cvt.rn.bf16x2.f32 %0, %1, %2;" : "=r"(r) : "f"(b), "f"(a));
    return r;
}
__device__ __forceinline__ uint32_t pack_h2(float a, float b) {
    uint32_t r;
    asm("cvt.rn.f16x2.f32 %0, %1, %2;" : "=r"(r) : "f"(b), "f"(a));
    return r;
}
// Residual pair from the already-packed hi pair (no F2FP round-trip).
__device__ __forceinline__ uint32_t pack_res2(float a, float b, uint32_t ph) {
    const float ra = a - __uint_as_float(ph << 16);
    const float rb = b - __uint_as_float(ph & 0xFFFF0000u);
    return pack_bf2(ra, rb);
}
__device__ __forceinline__ float ex2(float x) {
    float r; asm("ex2.approx.f32 %0, %1;" : "=f"(r) : "f"(x)); return r;
}
__device__ __forceinline__ float rcp(float x) {
    float r; asm("rcp.approx.f32 %0, %1;" : "=f"(r) : "f"(x)); return r;
}

// ---------------------------------------------------------------------------
// split fp32 -> bf16 hi + bf16 lo. x variant + fused 4-weight variant.
// ---------------------------------------------------------------------------
__global__ __launch_bounds__(256) void split_kernel(
    const float* __restrict__ src, __nv_bfloat16* __restrict__ hi,
    __nv_bfloat16* __restrict__ lo, int n)
{
    int i = (blockIdx.x * 256 + threadIdx.x) * 4;
    if (i >= n) return;
    float4 v = *(const float4*)(src + i);
    uint32_t* ph = (uint32_t*)(hi + i);
    uint32_t* pl = (uint32_t*)(lo + i);
    uint32_t h0 = pack_bf2(v.x, v.y), h1 = pack_bf2(v.z, v.w);
    ph[0] = h0; ph[1] = h1;
    pl[0] = pack_res2(v.x, v.y, h0);
    pl[1] = pack_res2(v.z, v.w, h1);
}

__global__ __launch_bounds__(256) void split_w_kernel(
    const float* __restrict__ w0, const float* __restrict__ w1,
    const float* __restrict__ w2, const float* __restrict__ w3)
{
    const int sel = blockIdx.y;
    const float* src = (sel == 0) ? w0 : (sel == 1) ? w1 : (sel == 2) ? w2 : w3;
    const size_t NW = (size_t)D_MODEL * D_MODEL;
    __nv_bfloat16* hi = &g_whi[0][0] + sel * NW;
    __nv_bfloat16* lo = &g_wlo[0][0] + sel * NW;
    int i = (blockIdx.x * 256 + threadIdx.x) * 4;
    float4 v = *(const float4*)(src + i);
    uint32_t* ph = (uint32_t*)(hi + i);
    uint32_t* pl = (uint32_t*)(lo + i);
    uint32_t h0 = pack_bf2(v.x, v.y), h1 = pack_bf2(v.z, v.w);
    ph[0] = h0; ph[1] = h1;
    pl[0] = pack_res2(v.x, v.y, h0);
    pl[1] = pack_res2(v.z, v.w, h1);
}

// ---------------------------------------------------------------------------
// Shared HMMA split-bf16 GEMM core: acc += A[m][k]*B[n][k], 3-pass hh+lh+hl.
// CTA 128x128, BK=32, 256 threads (8 warps, 32m x 64n).
// 2-stage cp.async pipeline, ONE __syncthreads per K-step.
// ---------------------------------------------------------------------------
#define GSTAGE 32768
#define GSMEM  (2 * GSTAGE)
#define NCHUNK 32

__device__ __forceinline__ void load_chunk(
    uint32_t sbase, int tid, int m0, int n0, int kc,
    const __nv_bfloat16* __restrict__ Ahi, const __nv_bfloat16* __restrict__ Alo,
    const __nv_bfloat16* __restrict__ Bhi, const __nv_bfloat16* __restrict__ Blo)
{
    const int row = tid >> 2;
    const int chunk = tid & 3;
    const int kcol = kc * 32 + chunk * 8;
#pragma unroll
    for (int u = 0; u < 2; u++) {
        const int r = row + u * 64;
        const uint32_t so = (uint32_t)(r * 64 + ((chunk ^ ((r >> 1) & 3)) << 4));
        CP16(sbase + so,         (const char*)(Ahi + (size_t)(m0 + r) * 1024 + kcol));
        CP16(sbase + 8192 + so,  (const char*)(Alo + (size_t)(m0 + r) * 1024 + kcol));
        CP16(sbase + 16384 + so, (const char*)(Bhi + (size_t)(n0 + r) * 1024 + kcol));
        CP16(sbase + 24576 + so, (const char*)(Blo + (size_t)(n0 + r) * 1024 + kcol));
    }
}

__device__ __forceinline__ void gemm_core(
    uint32_t sb, int tid, int m0, int n0,
    const __nv_bfloat16* __restrict__ Ahi, const __nv_bfloat16* __restrict__ Alo,
    const __nv_bfloat16* __restrict__ Bhi, const __nv_bfloat16* __restrict__ Blo,
    float acc[2][8][4])
{
    const int wid = tid >> 5;
    const int lid = tid & 31;
    const int warp_m = (wid >> 1) * 32;
    const int warp_n = (wid & 1) * 64;
    const int sub = lid >> 3;
    const int r8  = lid & 7;

    load_chunk(sb, tid, m0, n0, 0, Ahi, Alo, Bhi, Blo);
    CP_COMMIT();

    for (int kc = 0; kc < NCHUNK; kc++) {
        CP_WAIT(0);
        __syncthreads();
        if (kc + 1 < NCHUNK) {
            load_chunk(sb + (uint32_t)((kc + 1) & 1) * GSTAGE, tid, m0, n0, kc + 1,
                       Ahi, Alo, Bhi, Blo);
            CP_COMMIT();
        }
        const uint32_t cur = sb + (uint32_t)(kc & 1) * GSTAGE;

#pragma unroll
        for (int ks = 0; ks < 2; ks++) {
            const int kchunk = ks * 2 + (sub >> 1);
            uint32_t ahi[2][4], alo[2][4], bfr[4][4];
            uint32_t bad[4];
#pragma unroll
            for (int mt = 0; mt < 2; mt++) {
                const int mr = warp_m + mt * 16 + ((sub & 1) << 3) + r8;
                const uint32_t ad = cur + (uint32_t)(mr * 64 + ((kchunk ^ ((mr >> 1) & 3)) << 4));
                LDMX4(ahi[mt], ad);
                LDMX4(alo[mt], ad + 8192);
            }
#pragma unroll
            for (int nt = 0; nt < 4; nt++) {
                const int nr = warp_n + nt * 16 + ((sub & 1) << 3) + r8;
                bad[nt] = cur + 16384 + (uint32_t)(nr * 64 + ((kchunk ^ ((nr >> 1) & 3)) << 4));
                LDMX4(bfr[nt], bad[nt]);
            }
#pragma unroll
            for (int mt = 0; mt < 2; mt++)
#pragma unroll
                for (int nt = 0; nt < 4; nt++) {
                    MMA_BF16(acc[mt][2 * nt + 0], ahi[mt], bfr[nt][0], bfr[nt][2]);
                    MMA_BF16(acc[mt][2 * nt + 1], ahi[mt], bfr[nt][1], bfr[nt][3]);
                    MMA_BF16(acc[mt][2 * nt + 0], alo[mt], bfr[nt][0], bfr[nt][2]);
                    MMA_BF16(acc[mt][2 * nt + 1], alo[mt], bfr[nt][1], bfr[nt][3]);
                }
#pragma unroll
            for (int nt = 0; nt < 4; nt++)
                LDMX4(bfr[nt], bad[nt] + 8192);
#pragma unroll
            for (int mt = 0; mt < 2; mt++)
#pragma unroll
                for (int nt = 0; nt < 4; nt++) {
                    MMA_BF16(acc[mt][2 * nt + 0], ahi[mt], bfr[nt][0], bfr[nt][2]);
                    MMA_BF16(acc[mt][2 * nt + 1], ahi[mt], bfr[nt][1], bfr[nt][3]);
                }
        }
    }
}

// Fused QKV projection: grid (24, 32); blockIdx.x -> {sel, n-block}.
// sel 0: Q bf16 hi/lo, pre-scaled by 0.125*log2e.  sel 1: K bf16 hi only.
// sel 2: V fp16 single.
__global__ __launch_bounds__(256) void gemm_qkv_kernel()
{
    extern __shared__ __align__(128) char smem[];
    const uint32_t sb = smem_u32(smem);
    const int tid = threadIdx.x;
    const int sel = blockIdx.x >> 3;
    const int n0 = (blockIdx.x & 7) * 128;
    const int m0 = blockIdx.y * 128;
    const size_t NW = (size_t)D_MODEL * D_MODEL;

    const __nv_bfloat16* Bhi = &g_whi[0][0] + sel * NW;
    const __nv_bfloat16* Blo = &g_wlo[0][0] + sel * NW;
    const float scale = (sel == 0) ? Q_PRESCALE : 1.0f;

    float acc[2][8][4];
#pragma unroll
    for (int a = 0; a < 2; a++)
#pragma unroll
        for (int b = 0; b < 8; b++)
#pragma unroll
            for (int c = 0; c < 4; c++) acc[a][b][c] = 0.f;

    gemm_core(sb, tid, m0, n0, g_xhi, g_xlo, Bhi, Blo, acc);

    const int wid = tid >> 5, lid = tid & 31;
    const int warp_m = (wid >> 1) * 32, warp_n = (wid & 1) * 64;
#pragma unroll
    for (int mt = 0; mt < 2; mt++) {
        const int mrow = m0 + warp_m + mt * 16 + (lid >> 2);
#pragma unroll
        for (int nt = 0; nt < 8; nt++) {
            const int ncol = n0 + warp_n + nt * 8 + 2 * (lid & 3);
            const float a0 = acc[mt][nt][0] * scale, a1 = acc[mt][nt][1] * scale;
            const float a2 = acc[mt][nt][2] * scale, a3 = acc[mt][nt][3] * scale;
            if (sel == 2) {
                *(uint32_t*)(g_vf + (size_t)mrow * 1024 + ncol)       = pack_h2(a0, a1);
                *(uint32_t*)(g_vf + (size_t)(mrow + 8) * 1024 + ncol) = pack_h2(a2, a3);
            } else {
                __nv_bfloat16* Chi = (sel == 0) ? g_qhi : g_khi;
                const uint32_t h0 = pack_bf2(a0, a1), h1 = pack_bf2(a2, a3);
                *(uint32_t*)(Chi + (size_t)mrow * 1024 + ncol) = h0;
                *(uint32_t*)(Chi + (size_t)(mrow + 8) * 1024 + ncol) = h1;
                if (sel == 0) {
                    *(uint32_t*)(g_qlo + (size_t)mrow * 1024 + ncol) = pack_res2(a0, a1, h0);
                    *(uint32_t*)(g_qlo + (size_t)(mrow + 8) * 1024 + ncol) = pack_res2(a2, a3, h1);
                }
            }
        }
    }
}

// Output projection: fp32 out + bias.
__global__ __launch_bounds__(256) void gemm_out_kernel(
    const float* __restrict__ bias, float* __restrict__ C)
{
    extern __shared__ __align__(128) char smem[];
    const uint32_t sb = smem_u32(smem);
    const int tid = threadIdx.x;
    const int n0 = blockIdx.x * 128;
    const int m0 = blockIdx.y * 128;
    const size_t NW = (size_t)D_MODEL * D_MODEL;

    float acc[2][8][4];
#pragma unroll
    for (int a = 0; a < 2; a++)
#pragma unroll
        for (int b = 0; b < 8; b++)
#pragma unroll
            for (int c = 0; c < 4; c++) acc[a][b][c] = 0.f;

    gemm_core(sb, tid, m0, n0, g_chi, g_clo, &g_whi[0][0] + 3 * NW, &g_wlo[0][0] + 3 * NW, acc);

    const int wid = tid >> 5, lid = tid & 31;
    const int warp_m = (wid >> 1) * 32, warp_n = (wid & 1) * 64;
#pragma unroll
    for (int mt = 0; mt < 2; mt++) {
        const int mrow = m0 + warp_m + mt * 16 + (lid >> 2);
#pragma unroll
        for (int nt = 0; nt < 8; nt++) {
            const int ncol = n0 + warp_n + nt * 8 + 2 * (lid & 3);
            const float b0 = bias[ncol], b1 = bias[ncol + 1];
            *(float2*)(C + (size_t)mrow * 1024 + ncol) =
                make_float2(acc[mt][nt][0] + b0, acc[mt][nt][1] + b1);
            *(float2*)(C + (size_t)(mrow + 8) * 1024 + ncol) =
                make_float2(acc[mt][nt][2] + b0, acc[mt][nt][3] + b1);
        }
    }
}

// ---------------------------------------------------------------------------
// Tensor-core flash attention (causal). CTA processes TWO q-blocks {63-p, p}
// (constant 65 K-tiles per CTA). 128 threads, launch_bounds(128,3).
// QK^T: 2-pass bf16 ((Qhi+Qlo)*Khi). PV: SINGLE-pass fp16 (P,V in fp16).
// MUFU ex2 softmax (Q pre-scaled by 0.125*log2e).
// 2-stage cp.async pipeline, 16KB stages (Khi bf16 | V fp16), ONE barrier
// per tile. Q staged in stage-1 region, consumed before kv1 lands.
// SMEM = 2 x 16KB = 32KB.
// ---------------------------------------------------------------------------
#define A_STSZ 16384
#define A_VF   8192
#define A_SMEM (2 * A_STSZ)   // 32768

__device__ __forceinline__ uint32_t aphys(int row, int chunk) {
    return (uint32_t)(row * 128 + (((chunk) ^ (row & 7)) << 4));
}

__device__ __forceinline__ void attn_load_kv(uint32_t st, int kb, int h, int tid) {
    const int r0 = tid >> 3;
    const int c  = tid & 7;
#pragma unroll
    for (int u = 0; u < 4; u++) {
        const int r = r0 + u * 16;
        const uint32_t so = aphys(r, c);
        const size_t gi = (size_t)(kb * 64 + r) * 1024 + h * 64 + c * 8;
        CP16(st + so,         (const char*)(g_khi + gi));
        CP16(st + A_VF + so,  (const char*)(g_vf + gi));
    }
}

__global__ __launch_bounds__(128, 3) void attn_kernel()
{
    extern __shared__ __align__(128) char smem[];
    const uint32_t sb = smem_u32(smem);
    const int tid = threadIdx.x;
    const int w = tid >> 5;
    const int l = tid & 31;
    const int p = blockIdx.x;           // 0..31 (pair index)
    const int h = blockIdx.y;

#pragma unroll 1
    for (int half = 0; half < 2; half++) {
        const int qb = half ? p : (63 - p);   // long block first
        const int q0 = qb * 64;
        const int nkt = qb + 1;

        // Prologue: Q (hi+lo, 16KB) into stage-1 region; KV tile 0 into stage-0.
        {
            const int r0 = tid >> 3;
            const int c  = tid & 7;
#pragma unroll
            for (int u = 0; u < 4; u++) {
                const int r = r0 + u * 16;
                const uint32_t so = aphys(r, c);
                const size_t gi = (size_t)(q0 + r) * 1024 + h * 64 + c * 8;
                CP16(sb + A_STSZ + so,        (const char*)(g_qhi + gi));
                CP16(sb + A_STSZ + 8192 + so, (const char*)(g_qlo + gi));
            }
        }
        attn_load_kv(sb, 0, h, tid);
        CP_COMMIT();
        CP_WAIT(0);
        __syncthreads();

        // Consume Q into register fragments, then free the stage-1 region.
        uint32_t qfh[4][4], qfl[4][4];
        {
            const int row = 16 * w + (l & 15);
#pragma unroll
            for (int ks = 0; ks < 4; ks++) {
                const uint32_t ad = sb + A_STSZ + aphys(row, 2 * ks + (l >> 4));
                LDMX4(qfh[ks], ad);
                LDMX4(qfl[ks], ad + 8192);
            }
        }
        __syncthreads();

        float O[8][4];
        float m0 = -INFINITY, m1 = -INFINITY, l0 = 0.f, l1 = 0.f;
#pragma unroll
        for (int nt = 0; nt < 8; nt++)
#pragma unroll
            for (int j = 0; j < 4; j++) O[nt][j] = 0.f;

        for (int kb = 0; kb < nkt; kb++) {
            if (kb > 0) {
                CP_WAIT(0);
                __syncthreads();
            }
            if (kb + 1 < nkt) {
                attn_load_kv(sb + (uint32_t)((kb + 1) & 1) * A_STSZ, kb + 1, h, tid);
                CP_COMMIT();
            }
            const uint32_t st = sb + (uint32_t)(kb & 1) * A_STSZ;

            // ---- S = Q K^T (2-pass: (Qhi+Qlo) * Khi) ----
            float s[8][4];
#pragma unroll
            for (int nt = 0; nt < 8; nt++)
#pragma unroll
                for (int j = 0; j < 4; j++) s[nt][j] = 0.f;

#pragma unroll
            for (int ks = 0; ks < 4; ks++) {
#pragma unroll
                for (int ntp = 0; ntp < 4; ntp++) {
                    const int nrow = ntp * 16 + (l & 15);
                    const uint32_t ad = st + aphys(nrow, 2 * ks + (l >> 4));
                    uint32_t bh[4];
                    LDMX4(bh, ad);
                    MMA_BF16(s[2 * ntp + 0], qfh[ks], bh[0], bh[2]);
                    MMA_BF16(s[2 * ntp + 1], qfh[ks], bh[1], bh[3]);
                    MMA_BF16(s[2 * ntp + 0], qfl[ks], bh[0], bh[2]);
                    MMA_BF16(s[2 * ntp + 1], qfl[ks], bh[1], bh[3]);
                }
            }

            // ---- causal mask (diagonal tile only) ----
            if (kb == qb) {
                const int rl0 = 16 * w + (l >> 2);
#pragma unroll
                for (int nt = 0; nt < 8; nt++) {
                    const int c0 = nt * 8 + 2 * (l & 3);
                    if (c0     > rl0    ) s[nt][0] = -INFINITY;
                    if (c0 + 1 > rl0    ) s[nt][1] = -INFINITY;
                    if (c0     > rl0 + 8) s[nt][2] = -INFINITY;
                    if (c0 + 1 > rl0 + 8) s[nt][3] = -INFINITY;
                }
            }

            // ---- online softmax in base-2 (rows l>>2 and l>>2 + 8) ----
            float mr0 = -INFINITY, mr1 = -INFINITY;
#pragma unroll
            for (int nt = 0; nt < 8; nt++) {
                mr0 = fmaxf(mr0, fmaxf(s[nt][0], s[nt][1]));
                mr1 = fmaxf(mr1, fmaxf(s[nt][2], s[nt][3]));
            }
            mr0 = fmaxf(mr0, __shfl_xor_sync(0xffffffffu, mr0, 1));
            mr0 = fmaxf(mr0, __shfl_xor_sync(0xffffffffu, mr0, 2));
            mr1 = fmaxf(mr1, __shfl_xor_sync(0xffffffffu, mr1, 1));
            mr1 = fmaxf(mr1, __shfl_xor_sync(0xffffffffu, mr1, 2));
            const float mn0 = fmaxf(m0, mr0);
            const float mn1 = fmaxf(m1, mr1);
            const float a0 = ex2(m0 - mn0);
            const float a1 = ex2(m1 - mn1);

            float sum0 = 0.f, sum1 = 0.f;
#pragma unroll
            for (int nt = 0; nt < 8; nt++) {
                s[nt][0] = ex2(s[nt][0] - mn0); sum0 += s[nt][0];
                s[nt][1] = ex2(s[nt][1] - mn0); sum0 += s[nt][1];
                s[nt][2] = ex2(s[nt][2] - mn1); sum1 += s[nt][2];
                s[nt][3] = ex2(s[nt][3] - mn1); sum1 += s[nt][3];
            }
            sum0 += __shfl_xor_sync(0xffffffffu, sum0, 1);
            sum0 += __shfl_xor_sync(0xffffffffu, sum0, 2);
            sum1 += __shfl_xor_sync(0xffffffffu, sum1, 1);
            sum1 += __shfl_xor_sync(0xffffffffu, sum1, 2);
            l0 = l0 * a0 + sum0;
            l1 = l1 * a1 + sum1;
            m0 = mn0; m1 = mn1;

#pragma unroll
            for (int nt = 0; nt < 8; nt++) {
                O[nt][0] *= a0; O[nt][1] *= a0;
                O[nt][2] *= a1; O[nt][3] *= a1;
            }

            // ---- O += P V (single-pass fp16), P packed from registers ----
#pragma unroll
            for (int ks = 0; ks < 4; ks++) {
                uint32_t ph[4];
                ph[0] = pack_h2(s[2 * ks][0],     s[2 * ks][1]);
                ph[1] = pack_h2(s[2 * ks][2],     s[2 * ks][3]);
                ph[2] = pack_h2(s[2 * ks + 1][0], s[2 * ks + 1][1]);
                ph[3] = pack_h2(s[2 * ks + 1][2], s[2 * ks + 1][3]);
                const int vrow = 16 * ks + (l & 15);
#pragma unroll
                for (int dtp = 0; dtp < 4; dtp++) {
                    const uint32_t ad = st + A_VF + aphys(vrow, 2 * dtp + (l >> 4));
                    uint32_t vf[4];
                    LDMX4T(vf, ad);
                    MMA_F16(O[2 * dtp + 0], ph, vf[0], vf[1]);
                    MMA_F16(O[2 * dtp + 1], ph, vf[2], vf[3]);
                }
            }
        }

        // ---- epilogue: ctx hi/lo bf16 ----
        const float i0 = rcp(l0);
        const float i1 = rcp(l1);
        const int rg0 = q0 + 16 * w + (l >> 2);
        const int cb = h * 64 + 2 * (l & 3);
#pragma unroll
        for (int nt = 0; nt < 8; nt++) {
            const float v00 = O[nt][0] * i0, v01 = O[nt][1] * i0;
            const float v10 = O[nt][2] * i1, v11 = O[nt][3] * i1;
            const size_t o0 = (size_t)rg0 * 1024 + cb + nt * 8;
            const size_t o1 = (size_t)(rg0 + 8) * 1024 + cb + nt * 8;
            const uint32_t h0 = pack_bf2(v00, v01), h1 = pack_bf2(v10, v11);
            *(uint32_t*)(g_chi + o0) = h0;
            *(uint32_t*)(g_clo + o0) = pack_res2(v00, v01, h0);
            *(uint32_t*)(g_chi + o1) = h1;
            *(uint32_t*)(g_clo + o1) = pack_res2(v10, v11, h1);
        }
        // Barrier between halves: all warps must finish reading the last KV
        // stage before the next half's prologue overwrites both stages.
        __syncthreads();
    }
}

// ---------------------------------------------------------------------------
extern "C" void kernel_launch(void* const* d_in, const int* in_sizes, int n_in,
                              void* d_out, int out_size)
{
    const float* x  = (const float*)d_in[0];
    const float* Wq = (const float*)d_in[1];
    const float* Wk = (const float*)d_in[2];
    const float* Wv = (const float*)d_in[3];
    const float* Wo = (const float*)d_in[4];
    const float* bo = (const float*)d_in[5];
    float* out = (float*)d_out;

    __nv_bfloat16 *xhi, *xlo;
    cudaGetSymbolAddress((void**)&xhi, g_xhi);
    cudaGetSymbolAddress((void**)&xlo, g_xlo);

    const int NX = N_TOK * D_MODEL;       // 4M
    const int NW = D_MODEL * D_MODEL;     // 1M

    split_kernel<<<NX / 1024, 256>>>(x, xhi, xlo, NX);
    split_w_kernel<<<dim3(NW / 1024, 4), 256>>>(Wq, Wk, Wv, Wo);

    cudaFuncSetAttribute(gemm_qkv_kernel, cudaFuncAttributeMaxDynamicSharedMemorySize, GSMEM);
    cudaFuncSetAttribute(gemm_out_kernel, cudaFuncAttributeMaxDynamicSharedMemorySize, GSMEM);

    gemm_qkv_kernel<<<dim3(24, 32), 256, GSMEM>>>();

    cudaFuncSetAttribute(attn_kernel, cudaFuncAttributeMaxDynamicSharedMemorySize, A_SMEM);
    attn_kernel<<<dim3(32, N_HEADS), 128, A_SMEM>>>();

    gemm_out_kernel<<<dim3(8, 32), 256, GSMEM>>>(bo, out);
}

// round 14
// speedup vs baseline: 2.3783x; 2.0175x over previous
#include <cuda_runtime.h>
#include <cuda_bf16.h>
#include <cuda_fp16.h>
#include <math.h>
#include <stdint.h>

#define N_TOK   4096
#define D_MODEL 1024
#define N_HEADS 16
#define HEAD_DIM 64

// 0.125 * log2(e): folded into Q at projection time so attention can use exp2.
#define Q_PRESCALE 0.18033688011112042f

// ---------------- device scratch (allocation-free rule) ----------------
__device__ __half g_xh[N_TOK * D_MODEL];
__device__ __half g_wh[4][D_MODEL * D_MODEL];
__device__ __half g_q[N_TOK * D_MODEL];
__device__ __half g_k[N_TOK * D_MODEL];
__device__ __half g_v[N_TOK * D_MODEL];
__device__ __half g_c[N_TOK * D_MODEL];

// ---------------- PTX helpers (sm_80-compatible; NO tcgen05) ------------
__device__ __forceinline__ uint32_t smem_u32(const void* p) {
    uint32_t a;
    asm("{ .reg .u64 t; cvta.to.shared.u64 t, %1; cvt.u32.u64 %0, t; }" : "=r"(a) : "l"(p));
    return a;
}

#define CP16(s, g) \
    asm volatile("cp.async.cg.shared.global [%0], [%1], 16;" :: "r"(s), "l"(g))
#define CP_COMMIT() asm volatile("cp.async.commit_group;" ::: "memory")
#define CP_WAIT(n)  asm volatile("cp.async.wait_group %0;" :: "n"(n) : "memory")

#define LDMX4(r, addr) \
    asm volatile("ldmatrix.sync.aligned.m8n8.x4.shared.b16 {%0,%1,%2,%3}, [%4];" \
        : "=r"((r)[0]), "=r"((r)[1]), "=r"((r)[2]), "=r"((r)[3]) : "r"(addr))

#define LDMX4T(r, addr) \
    asm volatile("ldmatrix.sync.aligned.m8n8.x4.trans.shared.b16 {%0,%1,%2,%3}, [%4];" \
        : "=r"((r)[0]), "=r"((r)[1]), "=r"((r)[2]), "=r"((r)[3]) : "r"(addr))

#define MMA_F16(d, a, b0, b1) \
    asm volatile("mma.sync.aligned.m16n8k16.row.col.f32.f16.f16.f32 " \
        "{%0,%1,%2,%3}, {%4,%5,%6,%7}, {%8,%9}, {%0,%1,%2,%3};" \
        : "+f"((d)[0]), "+f"((d)[1]), "+f"((d)[2]), "+f"((d)[3]) \
        : "r"((a)[0]), "r"((a)[1]), "r"((a)[2]), "r"((a)[3]), "r"(b0), "r"(b1))

__device__ __forceinline__ uint32_t pack_h2(float a, float b) {
    uint32_t r;
    asm("cvt.rn.f16x2.f32 %0, %1, %2;" : "=r"(r) : "f"(b), "f"(a));
    return r;
}
__device__ __forceinline__ float ex2(float x) {
    float r; asm("ex2.approx.f32 %0, %1;" : "=f"(r) : "f"(x)); return r;
}
__device__ __forceinline__ float rcp(float x) {
    float r; asm("rcp.approx.f32 %0, %1;" : "=f"(r) : "f"(x)); return r;
}

// ---------------------------------------------------------------------------
// convert fp32 -> fp16. x variant + fused 4-weight variant.
// ---------------------------------------------------------------------------
__global__ __launch_bounds__(256) void conv_x_kernel(
    const float* __restrict__ src, __half* __restrict__ dst, int n)
{
    int i = (blockIdx.x * 256 + threadIdx.x) * 4;
    if (i >= n) return;
    float4 v = *(const float4*)(src + i);
    uint32_t* pd = (uint32_t*)(dst + i);
    pd[0] = pack_h2(v.x, v.y);
    pd[1] = pack_h2(v.z, v.w);
}

__global__ __launch_bounds__(256) void conv_w_kernel(
    const float* __restrict__ w0, const float* __restrict__ w1,
    const float* __restrict__ w2, const float* __restrict__ w3)
{
    const int sel = blockIdx.y;
    const float* src = (sel == 0) ? w0 : (sel == 1) ? w1 : (sel == 2) ? w2 : w3;
    const size_t NW = (size_t)D_MODEL * D_MODEL;
    __half* dst = &g_wh[0][0] + sel * NW;
    int i = (blockIdx.x * 256 + threadIdx.x) * 4;
    float4 v = *(const float4*)(src + i);
    uint32_t* pd = (uint32_t*)(dst + i);
    pd[0] = pack_h2(v.x, v.y);
    pd[1] = pack_h2(v.z, v.w);
}

// ---------------------------------------------------------------------------
// HMMA fp16 single-pass GEMM core: acc += A[m][k]*B[n][k] (fp32 accum).
// CTA 128x128, BK=32, 256 threads (8 warps, 32m x 64n).
// 2-stage cp.async pipeline (16KB stages: A 8K | B 8K), ONE barrier/K-step.
// ---------------------------------------------------------------------------
#define GSTAGE 16384
#define GSMEM  (2 * GSTAGE)
#define NCHUNK 32

__device__ __forceinline__ void load_chunk(
    uint32_t sbase, int tid, int m0, int n0, int kc,
    const __half* __restrict__ A, const __half* __restrict__ B)
{
    const int row = tid >> 2;        // 0..63
    const int chunk = tid & 3;       // 16B chunk within 64B row
    const int kcol = kc * 32 + chunk * 8;
#pragma unroll
    for (int u = 0; u < 2; u++) {
        const int r = row + u * 64;
        const uint32_t so = (uint32_t)(r * 64 + ((chunk ^ ((r >> 1) & 3)) << 4));
        CP16(sbase + so,        (const char*)(A + (size_t)(m0 + r) * 1024 + kcol));
        CP16(sbase + 8192 + so, (const char*)(B + (size_t)(n0 + r) * 1024 + kcol));
    }
}

__device__ __forceinline__ void gemm_core(
    uint32_t sb, int tid, int m0, int n0,
    const __half* __restrict__ A, const __half* __restrict__ B,
    float acc[2][8][4])
{
    const int wid = tid >> 5;
    const int lid = tid & 31;
    const int warp_m = (wid >> 1) * 32;
    const int warp_n = (wid & 1) * 64;
    const int sub = lid >> 3;
    const int r8  = lid & 7;

    load_chunk(sb, tid, m0, n0, 0, A, B);
    CP_COMMIT();

    for (int kc = 0; kc < NCHUNK; kc++) {
        CP_WAIT(0);
        __syncthreads();
        if (kc + 1 < NCHUNK) {
            load_chunk(sb + (uint32_t)((kc + 1) & 1) * GSTAGE, tid, m0, n0, kc + 1, A, B);
            CP_COMMIT();
        }
        const uint32_t cur = sb + (uint32_t)(kc & 1) * GSTAGE;

#pragma unroll
        for (int ks = 0; ks < 2; ks++) {
            const int kchunk = ks * 2 + (sub >> 1);
            uint32_t af[2][4], bf[4][4];
#pragma unroll
            for (int mt = 0; mt < 2; mt++) {
                const int mr = warp_m + mt * 16 + ((sub & 1) << 3) + r8;
                LDMX4(af[mt], cur + (uint32_t)(mr * 64 + ((kchunk ^ ((mr >> 1) & 3)) << 4)));
            }
#pragma unroll
            for (int nt = 0; nt < 4; nt++) {
                const int nr = warp_n + nt * 16 + ((sub & 1) << 3) + r8;
                LDMX4(bf[nt], cur + 8192 + (uint32_t)(nr * 64 + ((kchunk ^ ((nr >> 1) & 3)) << 4)));
            }
#pragma unroll
            for (int mt = 0; mt < 2; mt++)
#pragma unroll
                for (int nt = 0; nt < 4; nt++) {
                    MMA_F16(acc[mt][2 * nt + 0], af[mt], bf[nt][0], bf[nt][2]);
                    MMA_F16(acc[mt][2 * nt + 1], af[mt], bf[nt][1], bf[nt][3]);
                }
        }
    }
}

// Fused QKV projection: grid (24, 32); blockIdx.x -> {sel, n-block}.
// sel 0: Q (pre-scaled by 0.125*log2e), 1: K, 2: V. All fp16 single.
__global__ __launch_bounds__(256) void gemm_qkv_kernel()
{
    extern __shared__ __align__(128) char smem[];
    const uint32_t sb = smem_u32(smem);
    const int tid = threadIdx.x;
    const int sel = blockIdx.x >> 3;
    const int n0 = (blockIdx.x & 7) * 128;
    const int m0 = blockIdx.y * 128;
    const size_t NW = (size_t)D_MODEL * D_MODEL;

    const __half* W = &g_wh[0][0] + sel * NW;
    __half* C = (sel == 0) ? g_q : (sel == 1) ? g_k : g_v;
    const float scale = (sel == 0) ? Q_PRESCALE : 1.0f;

    float acc[2][8][4];
#pragma unroll
    for (int a = 0; a < 2; a++)
#pragma unroll
        for (int b = 0; b < 8; b++)
#pragma unroll
            for (int c = 0; c < 4; c++) acc[a][b][c] = 0.f;

    gemm_core(sb, tid, m0, n0, g_xh, W, acc);

    const int wid = tid >> 5, lid = tid & 31;
    const int warp_m = (wid >> 1) * 32, warp_n = (wid & 1) * 64;
#pragma unroll
    for (int mt = 0; mt < 2; mt++) {
        const int mrow = m0 + warp_m + mt * 16 + (lid >> 2);
#pragma unroll
        for (int nt = 0; nt < 8; nt++) {
            const int ncol = n0 + warp_n + nt * 8 + 2 * (lid & 3);
            *(uint32_t*)(C + (size_t)mrow * 1024 + ncol) =
                pack_h2(acc[mt][nt][0] * scale, acc[mt][nt][1] * scale);
            *(uint32_t*)(C + (size_t)(mrow + 8) * 1024 + ncol) =
                pack_h2(acc[mt][nt][2] * scale, acc[mt][nt][3] * scale);
        }
    }
}

// Output projection: fp32 out + bias.
__global__ __launch_bounds__(256) void gemm_out_kernel(
    const float* __restrict__ bias, float* __restrict__ C)
{
    extern __shared__ __align__(128) char smem[];
    const uint32_t sb = smem_u32(smem);
    const int tid = threadIdx.x;
    const int n0 = blockIdx.x * 128;
    const int m0 = blockIdx.y * 128;
    const size_t NW = (size_t)D_MODEL * D_MODEL;

    float acc[2][8][4];
#pragma unroll
    for (int a = 0; a < 2; a++)
#pragma unroll
        for (int b = 0; b < 8; b++)
#pragma unroll
            for (int c = 0; c < 4; c++) acc[a][b][c] = 0.f;

    gemm_core(sb, tid, m0, n0, g_c, &g_wh[0][0] + 3 * NW, acc);

    const int wid = tid >> 5, lid = tid & 31;
    const int warp_m = (wid >> 1) * 32, warp_n = (wid & 1) * 64;
#pragma unroll
    for (int mt = 0; mt < 2; mt++) {
        const int mrow = m0 + warp_m + mt * 16 + (lid >> 2);
#pragma unroll
        for (int nt = 0; nt < 8; nt++) {
            const int ncol = n0 + warp_n + nt * 8 + 2 * (lid & 3);
            const float b0 = bias[ncol], b1 = bias[ncol + 1];
            *(float2*)(C + (size_t)mrow * 1024 + ncol) =
                make_float2(acc[mt][nt][0] + b0, acc[mt][nt][1] + b1);
            *(float2*)(C + (size_t)(mrow + 8) * 1024 + ncol) =
                make_float2(acc[mt][nt][2] + b0, acc[mt][nt][3] + b1);
        }
    }
}

// ---------------------------------------------------------------------------
// Tensor-core flash attention (causal), full fp16. CTA = TWO q-blocks
// {63-p, p} (constant 65 K-tiles). 128 threads, launch_bounds(128,3).
// QK^T: 1-pass fp16. PV: 1-pass fp16. MUFU ex2 softmax (Q pre-scaled).
// 2-stage cp.async, 16KB stages (K 8K | V 8K), ONE barrier per tile.
// Q (8KB fp16) staged in the stage-1 K region, consumed before kv1 lands.
// ---------------------------------------------------------------------------
#define A_STSZ 16384
#define A_VF   8192
#define A_SMEM (2 * A_STSZ)   // 32768

__device__ __forceinline__ uint32_t aphys(int row, int chunk) {
    return (uint32_t)(row * 128 + (((chunk) ^ (row & 7)) << 4));
}

__device__ __forceinline__ void attn_load_kv(uint32_t st, int kb, int h, int tid) {
    const int r0 = tid >> 3;
    const int c  = tid & 7;
#pragma unroll
    for (int u = 0; u < 4; u++) {
        const int r = r0 + u * 16;
        const uint32_t so = aphys(r, c);
        const size_t gi = (size_t)(kb * 64 + r) * 1024 + h * 64 + c * 8;
        CP16(st + so,        (const char*)(g_k + gi));
        CP16(st + A_VF + so, (const char*)(g_v + gi));
    }
}

__global__ __launch_bounds__(128, 3) void attn_kernel()
{
    extern __shared__ __align__(128) char smem[];
    const uint32_t sb = smem_u32(smem);
    const int tid = threadIdx.x;
    const int w = tid >> 5;
    const int l = tid & 31;
    const int p = blockIdx.x;           // 0..31 (pair index)
    const int h = blockIdx.y;

#pragma unroll 1
    for (int half = 0; half < 2; half++) {
        const int qb = half ? p : (63 - p);   // long block first
        const int q0 = qb * 64;
        const int nkt = qb + 1;

        // Prologue: Q (8KB) into stage-1 K region; KV tile 0 into stage-0.
        {
            const int r0 = tid >> 3;
            const int c  = tid & 7;
#pragma unroll
            for (int u = 0; u < 4; u++) {
                const int r = r0 + u * 16;
                const uint32_t so = aphys(r, c);
                CP16(sb + A_STSZ + so,
                     (const char*)(g_q + (size_t)(q0 + r) * 1024 + h * 64 + c * 8));
            }
        }
        attn_load_kv(sb, 0, h, tid);
        CP_COMMIT();
        CP_WAIT(0);
        __syncthreads();

        // Consume Q into register fragments, then free the stage-1 region.
        uint32_t qf[4][4];
        {
            const int row = 16 * w + (l & 15);
#pragma unroll
            for (int ks = 0; ks < 4; ks++)
                LDMX4(qf[ks], sb + A_STSZ + aphys(row, 2 * ks + (l >> 4)));
        }
        __syncthreads();

        float O[8][4];
        float m0 = -INFINITY, m1 = -INFINITY, l0 = 0.f, l1 = 0.f;
#pragma unroll
        for (int nt = 0; nt < 8; nt++)
#pragma unroll
            for (int j = 0; j < 4; j++) O[nt][j] = 0.f;

        for (int kb = 0; kb < nkt; kb++) {
            if (kb > 0) {
                CP_WAIT(0);
                __syncthreads();
            }
            if (kb + 1 < nkt) {
                attn_load_kv(sb + (uint32_t)((kb + 1) & 1) * A_STSZ, kb + 1, h, tid);
                CP_COMMIT();
            }
            const uint32_t st = sb + (uint32_t)(kb & 1) * A_STSZ;

            // ---- S = Q K^T (single-pass fp16) ----
            float s[8][4];
#pragma unroll
            for (int nt = 0; nt < 8; nt++)
#pragma unroll
                for (int j = 0; j < 4; j++) s[nt][j] = 0.f;

#pragma unroll
            for (int ks = 0; ks < 4; ks++) {
#pragma unroll
                for (int ntp = 0; ntp < 4; ntp++) {
                    const int nrow = ntp * 16 + (l & 15);
                    uint32_t bh[4];
                    LDMX4(bh, st + aphys(nrow, 2 * ks + (l >> 4)));
                    MMA_F16(s[2 * ntp + 0], qf[ks], bh[0], bh[2]);
                    MMA_F16(s[2 * ntp + 1], qf[ks], bh[1], bh[3]);
                }
            }

            // ---- causal mask (diagonal tile only) ----
            if (kb == qb) {
                const int rl0 = 16 * w + (l >> 2);
#pragma unroll
                for (int nt = 0; nt < 8; nt++) {
                    const int c0 = nt * 8 + 2 * (l & 3);
                    if (c0     > rl0    ) s[nt][0] = -INFINITY;
                    if (c0 + 1 > rl0    ) s[nt][1] = -INFINITY;
                    if (c0     > rl0 + 8) s[nt][2] = -INFINITY;
                    if (c0 + 1 > rl0 + 8) s[nt][3] = -INFINITY;
                }
            }

            // ---- online softmax in base-2 (rows l>>2 and l>>2 + 8) ----
            float mr0 = -INFINITY, mr1 = -INFINITY;
#pragma unroll
            for (int nt = 0; nt < 8; nt++) {
                mr0 = fmaxf(mr0, fmaxf(s[nt][0], s[nt][1]));
                mr1 = fmaxf(mr1, fmaxf(s[nt][2], s[nt][3]));
            }
            mr0 = fmaxf(mr0, __shfl_xor_sync(0xffffffffu, mr0, 1));
            mr0 = fmaxf(mr0, __shfl_xor_sync(0xffffffffu, mr0, 2));
            mr1 = fmaxf(mr1, __shfl_xor_sync(0xffffffffu, mr1, 1));
            mr1 = fmaxf(mr1, __shfl_xor_sync(0xffffffffu, mr1, 2));
            const float mn0 = fmaxf(m0, mr0);
            const float mn1 = fmaxf(m1, mr1);
            const float a0 = ex2(m0 - mn0);
            const float a1 = ex2(m1 - mn1);

            float sum0 = 0.f, sum1 = 0.f;
#pragma unroll
            for (int nt = 0; nt < 8; nt++) {
                s[nt][0] = ex2(s[nt][0] - mn0); sum0 += s[nt][0];
                s[nt][1] = ex2(s[nt][1] - mn0); sum0 += s[nt][1];
                s[nt][2] = ex2(s[nt][2] - mn1); sum1 += s[nt][2];
                s[nt][3] = ex2(s[nt][3] - mn1); sum1 += s[nt][3];
            }
            sum0 += __shfl_xor_sync(0xffffffffu, sum0, 1);
            sum0 += __shfl_xor_sync(0xffffffffu, sum0, 2);
            sum1 += __shfl_xor_sync(0xffffffffu, sum1, 1);
            sum1 += __shfl_xor_sync(0xffffffffu, sum1, 2);
            l0 = l0 * a0 + sum0;
            l1 = l1 * a1 + sum1;
            m0 = mn0; m1 = mn1;

#pragma unroll
            for (int nt = 0; nt < 8; nt++) {
                O[nt][0] *= a0; O[nt][1] *= a0;
                O[nt][2] *= a1; O[nt][3] *= a1;
            }

            // ---- O += P V (single-pass fp16), P packed from registers ----
#pragma unroll
            for (int ks = 0; ks < 4; ks++) {
                uint32_t ph[4];
                ph[0] = pack_h2(s[2 * ks][0],     s[2 * ks][1]);
                ph[1] = pack_h2(s[2 * ks][2],     s[2 * ks][3]);
                ph[2] = pack_h2(s[2 * ks + 1][0], s[2 * ks + 1][1]);
                ph[3] = pack_h2(s[2 * ks + 1][2], s[2 * ks + 1][3]);
                const int vrow = 16 * ks + (l & 15);
#pragma unroll
                for (int dtp = 0; dtp < 4; dtp++) {
                    uint32_t vf[4];
                    LDMX4T(vf, st + A_VF + aphys(vrow, 2 * dtp + (l >> 4)));
                    MMA_F16(O[2 * dtp + 0], ph, vf[0], vf[1]);
                    MMA_F16(O[2 * dtp + 1], ph, vf[2], vf[3]);
                }
            }
        }

        // ---- epilogue: ctx fp16 ----
        const float i0 = rcp(l0);
        const float i1 = rcp(l1);
        const int rg0 = q0 + 16 * w + (l >> 2);
        const int cb = h * 64 + 2 * (l & 3);
#pragma unroll
        for (int nt = 0; nt < 8; nt++) {
            const size_t o0 = (size_t)rg0 * 1024 + cb + nt * 8;
            const size_t o1 = (size_t)(rg0 + 8) * 1024 + cb + nt * 8;
            *(uint32_t*)(g_c + o0) = pack_h2(O[nt][0] * i0, O[nt][1] * i0);
            *(uint32_t*)(g_c + o1) = pack_h2(O[nt][2] * i1, O[nt][3] * i1);
        }
        // Barrier between halves: all warps must finish reading the last KV
        // stage before the next half's prologue overwrites both stages.
        __syncthreads();
    }
}

// ---------------------------------------------------------------------------
extern "C" void kernel_launch(void* const* d_in, const int* in_sizes, int n_in,
                              void* d_out, int out_size)
{
    const float* x  = (const float*)d_in[0];
    const float* Wq = (const float*)d_in[1];
    const float* Wk = (const float*)d_in[2];
    const float* Wv = (const float*)d_in[3];
    const float* Wo = (const float*)d_in[4];
    const float* bo = (const float*)d_in[5];
    float* out = (float*)d_out;

    __half* xh;
    cudaGetSymbolAddress((void**)&xh, g_xh);

    const int NX = N_TOK * D_MODEL;       // 4M
    const int NW = D_MODEL * D_MODEL;     // 1M

    conv_x_kernel<<<NX / 1024, 256>>>(x, xh, NX);
    conv_w_kernel<<<dim3(NW / 1024, 4), 256>>>(Wq, Wk, Wv, Wo);

    cudaFuncSetAttribute(gemm_qkv_kernel, cudaFuncAttributeMaxDynamicSharedMemorySize, GSMEM);
    cudaFuncSetAttribute(gemm_out_kernel, cudaFuncAttributeMaxDynamicSharedMemorySize, GSMEM);

    gemm_qkv_kernel<<<dim3(24, 32), 256, GSMEM>>>();

    cudaFuncSetAttribute(attn_kernel, cudaFuncAttributeMaxDynamicSharedMemorySize, A_SMEM);
    attn_kernel<<<dim3(32, N_HEADS), 128, A_SMEM>>>();

    gemm_out_kernel<<<dim3(8, 32), 256, GSMEM>>>(bo, out);
}

// round 15
// speedup vs baseline: 2.5478x; 1.0712x over previous
#include <cuda_runtime.h>
#include <cuda_bf16.h>
#include <cuda_fp16.h>
#include <math.h>
#include <stdint.h>

#define N_TOK   4096
#define D_MODEL 1024
#define N_HEADS 16
#define HEAD_DIM 64

// 0.125 * log2(e): folded into Q at projection time so attention can use exp2.
#define Q_PRESCALE 0.18033688011112042f
#define ONES_H2 0x3C003C00u   // fp16x2 (1.0, 1.0)

// ---------------- device scratch (allocation-free rule) ----------------
__device__ __half g_xh[N_TOK * D_MODEL];
__device__ __half g_wh[4][D_MODEL * D_MODEL];
__device__ __half g_q[N_TOK * D_MODEL];
__device__ __half g_k[N_TOK * D_MODEL];
__device__ __half g_v[N_TOK * D_MODEL];
__device__ __half g_c[N_TOK * D_MODEL];

// ---------------- PTX helpers (sm_80-compatible; NO tcgen05) ------------
__device__ __forceinline__ uint32_t smem_u32(const void* p) {
    uint32_t a;
    asm("{ .reg .u64 t; cvta.to.shared.u64 t, %1; cvt.u32.u64 %0, t; }" : "=r"(a) : "l"(p));
    return a;
}

#define CP16(s, g) \
    asm volatile("cp.async.cg.shared.global [%0], [%1], 16;" :: "r"(s), "l"(g))
#define CP_COMMIT() asm volatile("cp.async.commit_group;" ::: "memory")
#define CP_WAIT(n)  asm volatile("cp.async.wait_group %0;" :: "n"(n) : "memory")

#define LDMX4(r, addr) \
    asm volatile("ldmatrix.sync.aligned.m8n8.x4.shared.b16 {%0,%1,%2,%3}, [%4];" \
        : "=r"((r)[0]), "=r"((r)[1]), "=r"((r)[2]), "=r"((r)[3]) : "r"(addr))

#define LDMX4T(r, addr) \
    asm volatile("ldmatrix.sync.aligned.m8n8.x4.trans.shared.b16 {%0,%1,%2,%3}, [%4];" \
        : "=r"((r)[0]), "=r"((r)[1]), "=r"((r)[2]), "=r"((r)[3]) : "r"(addr))

#define MMA_F16(d, a, b0, b1) \
    asm volatile("mma.sync.aligned.m16n8k16.row.col.f32.f16.f16.f32 " \
        "{%0,%1,%2,%3}, {%4,%5,%6,%7}, {%8,%9}, {%0,%1,%2,%3};" \
        : "+f"((d)[0]), "+f"((d)[1]), "+f"((d)[2]), "+f"((d)[3]) \
        : "r"((a)[0]), "r"((a)[1]), "r"((a)[2]), "r"((a)[3]), "r"(b0), "r"(b1))

__device__ __forceinline__ uint32_t pack_h2(float a, float b) {
    uint32_t r;
    asm("cvt.rn.f16x2.f32 %0, %1, %2;" : "=r"(r) : "f"(b), "f"(a));
    return r;
}
__device__ __forceinline__ uint32_t ex2_h2(uint32_t x) {
    uint32_t r;
    asm("ex2.approx.f16x2 %0, %1;" : "=r"(r) : "r"(x));
    return r;
}
__device__ __forceinline__ float ex2(float x) {
    float r; asm("ex2.approx.f32 %0, %1;" : "=f"(r) : "f"(x)); return r;
}
__device__ __forceinline__ float rcp(float x) {
    float r; asm("rcp.approx.f32 %0, %1;" : "=f"(r) : "f"(x)); return r;
}

// ---------------------------------------------------------------------------
// convert fp32 -> fp16: one fused launch. grid (1024, 8):
// y 0..3 -> weights, y 4..7 -> quarter of x.
// ---------------------------------------------------------------------------
__global__ __launch_bounds__(256) void conv_all_kernel(
    const float* __restrict__ x,
    const float* __restrict__ w0, const float* __restrict__ w1,
    const float* __restrict__ w2, const float* __restrict__ w3)
{
    const int sel = blockIdx.y;
    const size_t NW = (size_t)D_MODEL * D_MODEL;
    const float* src;
    __half* dst;
    if (sel < 4) {
        src = (sel == 0) ? w0 : (sel == 1) ? w1 : (sel == 2) ? w2 : w3;
        dst = &g_wh[0][0] + sel * NW;
    } else {
        src = x + (size_t)(sel - 4) * NW;
        dst = g_xh + (size_t)(sel - 4) * NW;
    }
    int i = (blockIdx.x * 256 + threadIdx.x) * 4;
    float4 v = *(const float4*)(src + i);
    uint32_t* pd = (uint32_t*)(dst + i);
    pd[0] = pack_h2(v.x, v.y);
    pd[1] = pack_h2(v.z, v.w);
}

// ---------------------------------------------------------------------------
// HMMA fp16 single-pass GEMM core: acc += A[m][k]*B[n][k] (fp32 accum).
// CTA 128x128, BK=32, 256 threads (8 warps, 32m x 64n).
// 2-stage cp.async pipeline (16KB stages: A 8K | B 8K), ONE barrier/K-step.
// ---------------------------------------------------------------------------
#define GSTAGE 16384
#define GSMEM  (2 * GSTAGE)
#define NCHUNK 32

__device__ __forceinline__ void load_chunk(
    uint32_t sbase, int tid, int m0, int n0, int kc,
    const __half* __restrict__ A, const __half* __restrict__ B)
{
    const int row = tid >> 2;
    const int chunk = tid & 3;
    const int kcol = kc * 32 + chunk * 8;
#pragma unroll
    for (int u = 0; u < 2; u++) {
        const int r = row + u * 64;
        const uint32_t so = (uint32_t)(r * 64 + ((chunk ^ ((r >> 1) & 3)) << 4));
        CP16(sbase + so,        (const char*)(A + (size_t)(m0 + r) * 1024 + kcol));
        CP16(sbase + 8192 + so, (const char*)(B + (size_t)(n0 + r) * 1024 + kcol));
    }
}

__device__ __forceinline__ void gemm_core(
    uint32_t sb, int tid, int m0, int n0,
    const __half* __restrict__ A, const __half* __restrict__ B,
    float acc[2][8][4])
{
    const int wid = tid >> 5;
    const int lid = tid & 31;
    const int warp_m = (wid >> 1) * 32;
    const int warp_n = (wid & 1) * 64;
    const int sub = lid >> 3;
    const int r8  = lid & 7;

    load_chunk(sb, tid, m0, n0, 0, A, B);
    CP_COMMIT();

    for (int kc = 0; kc < NCHUNK; kc++) {
        CP_WAIT(0);
        __syncthreads();
        if (kc + 1 < NCHUNK) {
            load_chunk(sb + (uint32_t)((kc + 1) & 1) * GSTAGE, tid, m0, n0, kc + 1, A, B);
            CP_COMMIT();
        }
        const uint32_t cur = sb + (uint32_t)(kc & 1) * GSTAGE;

#pragma unroll
        for (int ks = 0; ks < 2; ks++) {
            const int kchunk = ks * 2 + (sub >> 1);
            uint32_t af[2][4], bf[4][4];
#pragma unroll
            for (int mt = 0; mt < 2; mt++) {
                const int mr = warp_m + mt * 16 + ((sub & 1) << 3) + r8;
                LDMX4(af[mt], cur + (uint32_t)(mr * 64 + ((kchunk ^ ((mr >> 1) & 3)) << 4)));
            }
#pragma unroll
            for (int nt = 0; nt < 4; nt++) {
                const int nr = warp_n + nt * 16 + ((sub & 1) << 3) + r8;
                LDMX4(bf[nt], cur + 8192 + (uint32_t)(nr * 64 + ((kchunk ^ ((nr >> 1) & 3)) << 4)));
            }
#pragma unroll
            for (int mt = 0; mt < 2; mt++)
#pragma unroll
                for (int nt = 0; nt < 4; nt++) {
                    MMA_F16(acc[mt][2 * nt + 0], af[mt], bf[nt][0], bf[nt][2]);
                    MMA_F16(acc[mt][2 * nt + 1], af[mt], bf[nt][1], bf[nt][3]);
                }
        }
    }
}

// Fused QKV projection: grid (24, 32); blockIdx.x -> {sel, n-block}.
__global__ __launch_bounds__(256) void gemm_qkv_kernel()
{
    extern __shared__ __align__(128) char smem[];
    const uint32_t sb = smem_u32(smem);
    const int tid = threadIdx.x;
    const int sel = blockIdx.x >> 3;
    const int n0 = (blockIdx.x & 7) * 128;
    const int m0 = blockIdx.y * 128;
    const size_t NW = (size_t)D_MODEL * D_MODEL;

    const __half* W = &g_wh[0][0] + sel * NW;
    __half* C = (sel == 0) ? g_q : (sel == 1) ? g_k : g_v;
    const float scale = (sel == 0) ? Q_PRESCALE : 1.0f;

    float acc[2][8][4];
#pragma unroll
    for (int a = 0; a < 2; a++)
#pragma unroll
        for (int b = 0; b < 8; b++)
#pragma unroll
            for (int c = 0; c < 4; c++) acc[a][b][c] = 0.f;

    gemm_core(sb, tid, m0, n0, g_xh, W, acc);

    const int wid = tid >> 5, lid = tid & 31;
    const int warp_m = (wid >> 1) * 32, warp_n = (wid & 1) * 64;
#pragma unroll
    for (int mt = 0; mt < 2; mt++) {
        const int mrow = m0 + warp_m + mt * 16 + (lid >> 2);
#pragma unroll
        for (int nt = 0; nt < 8; nt++) {
            const int ncol = n0 + warp_n + nt * 8 + 2 * (lid & 3);
            *(uint32_t*)(C + (size_t)mrow * 1024 + ncol) =
                pack_h2(acc[mt][nt][0] * scale, acc[mt][nt][1] * scale);
            *(uint32_t*)(C + (size_t)(mrow + 8) * 1024 + ncol) =
                pack_h2(acc[mt][nt][2] * scale, acc[mt][nt][3] * scale);
        }
    }
}

// Output projection: fp32 out + bias.
__global__ __launch_bounds__(256) void gemm_out_kernel(
    const float* __restrict__ bias, float* __restrict__ C)
{
    extern __shared__ __align__(128) char smem[];
    const uint32_t sb = smem_u32(smem);
    const int tid = threadIdx.x;
    const int n0 = blockIdx.x * 128;
    const int m0 = blockIdx.y * 128;
    const size_t NW = (size_t)D_MODEL * D_MODEL;

    float acc[2][8][4];
#pragma unroll
    for (int a = 0; a < 2; a++)
#pragma unroll
        for (int b = 0; b < 8; b++)
#pragma unroll
            for (int c = 0; c < 4; c++) acc[a][b][c] = 0.f;

    gemm_core(sb, tid, m0, n0, g_c, &g_wh[0][0] + 3 * NW, acc);

    const int wid = tid >> 5, lid = tid & 31;
    const int warp_m = (wid >> 1) * 32, warp_n = (wid & 1) * 64;
#pragma unroll
    for (int mt = 0; mt < 2; mt++) {
        const int mrow = m0 + warp_m + mt * 16 + (lid >> 2);
#pragma unroll
        for (int nt = 0; nt < 8; nt++) {
            const int ncol = n0 + warp_n + nt * 8 + 2 * (lid & 3);
            const float b0 = bias[ncol], b1 = bias[ncol + 1];
            *(float2*)(C + (size_t)mrow * 1024 + ncol) =
                make_float2(acc[mt][nt][0] + b0, acc[mt][nt][1] + b1);
            *(float2*)(C + (size_t)(mrow + 8) * 1024 + ncol) =
                make_float2(acc[mt][nt][2] + b0, acc[mt][nt][3] + b1);
        }
    }
}

// ---------------------------------------------------------------------------
// Tensor-core flash attention (causal), full fp16. CTA = TWO q-blocks
// {63-p, p} (constant 65 K-tiles). 128 threads, launch_bounds(128,3).
// QK^T / PV: 1-pass fp16. Softmax: fp16x2 MUFU exp2 (P emerges MMA-ready),
// row sums accumulated EXACTLY in fp32 via MMA against a ones B-fragment
// (no shuffle-adds, no fp32 exp). Q pre-scaled by 0.125*log2e.
// 2-stage cp.async, 16KB stages (K 8K | V 8K), ONE barrier per tile.
// ---------------------------------------------------------------------------
#define A_STSZ 16384
#define A_VF   8192
#define A_SMEM (2 * A_STSZ)   // 32768

__device__ __forceinline__ uint32_t aphys(int row, int chunk) {
    return (uint32_t)(row * 128 + (((chunk) ^ (row & 7)) << 4));
}

__device__ __forceinline__ void attn_load_kv(uint32_t st, int kb, int h, int tid) {
    const int r0 = tid >> 3;
    const int c  = tid & 7;
#pragma unroll
    for (int u = 0; u < 4; u++) {
        const int r = r0 + u * 16;
        const uint32_t so = aphys(r, c);
        const size_t gi = (size_t)(kb * 64 + r) * 1024 + h * 64 + c * 8;
        CP16(st + so,        (const char*)(g_k + gi));
        CP16(st + A_VF + so, (const char*)(g_v + gi));
    }
}

__global__ __launch_bounds__(128, 3) void attn_kernel()
{
    extern __shared__ __align__(128) char smem[];
    const uint32_t sb = smem_u32(smem);
    const int tid = threadIdx.x;
    const int w = tid >> 5;
    const int l = tid & 31;
    const int p = blockIdx.x;           // 0..31 (pair index)
    const int h = blockIdx.y;

#pragma unroll 1
    for (int half = 0; half < 2; half++) {
        const int qb = half ? p : (63 - p);   // long block first
        const int q0 = qb * 64;
        const int nkt = qb + 1;

        // Prologue: Q (8KB) into stage-1 K region; KV tile 0 into stage-0.
        {
            const int r0 = tid >> 3;
            const int c  = tid & 7;
#pragma unroll
            for (int u = 0; u < 4; u++) {
                const int r = r0 + u * 16;
                const uint32_t so = aphys(r, c);
                CP16(sb + A_STSZ + so,
                     (const char*)(g_q + (size_t)(q0 + r) * 1024 + h * 64 + c * 8));
            }
        }
        attn_load_kv(sb, 0, h, tid);
        CP_COMMIT();
        CP_WAIT(0);
        __syncthreads();

        // Consume Q into register fragments, then free the stage-1 region.
        uint32_t qf[4][4];
        {
            const int row = 16 * w + (l & 15);
#pragma unroll
            for (int ks = 0; ks < 4; ks++)
                LDMX4(qf[ks], sb + A_STSZ + aphys(row, 2 * ks + (l >> 4)));
        }
        __syncthreads();

        float O[8][4];
        float lsum[4];
        float m0 = -INFINITY, m1 = -INFINITY;
#pragma unroll
        for (int nt = 0; nt < 8; nt++)
#pragma unroll
            for (int j = 0; j < 4; j++) O[nt][j] = 0.f;
#pragma unroll
        for (int j = 0; j < 4; j++) lsum[j] = 0.f;

        for (int kb = 0; kb < nkt; kb++) {
            if (kb > 0) {
                CP_WAIT(0);
                __syncthreads();
            }
            if (kb + 1 < nkt) {
                attn_load_kv(sb + (uint32_t)((kb + 1) & 1) * A_STSZ, kb + 1, h, tid);
                CP_COMMIT();
            }
            const uint32_t st = sb + (uint32_t)(kb & 1) * A_STSZ;

            // ---- S = Q K^T (single-pass fp16) ----
            float s[8][4];
#pragma unroll
            for (int nt = 0; nt < 8; nt++)
#pragma unroll
                for (int j = 0; j < 4; j++) s[nt][j] = 0.f;

#pragma unroll
            for (int ks = 0; ks < 4; ks++) {
#pragma unroll
                for (int ntp = 0; ntp < 4; ntp++) {
                    const int nrow = ntp * 16 + (l & 15);
                    uint32_t bh[4];
                    LDMX4(bh, st + aphys(nrow, 2 * ks + (l >> 4)));
                    MMA_F16(s[2 * ntp + 0], qf[ks], bh[0], bh[2]);
                    MMA_F16(s[2 * ntp + 1], qf[ks], bh[1], bh[3]);
                }
            }

            // ---- causal mask (diagonal tile only) ----
            if (kb == qb) {
                const int rl0 = 16 * w + (l >> 2);
#pragma unroll
                for (int nt = 0; nt < 8; nt++) {
                    const int c0 = nt * 8 + 2 * (l & 3);
                    if (c0     > rl0    ) s[nt][0] = -INFINITY;
                    if (c0 + 1 > rl0    ) s[nt][1] = -INFINITY;
                    if (c0     > rl0 + 8) s[nt][2] = -INFINITY;
                    if (c0 + 1 > rl0 + 8) s[nt][3] = -INFINITY;
                }
            }

            // ---- online max (rows l>>2 and l>>2 + 8) ----
            float mr0 = -INFINITY, mr1 = -INFINITY;
#pragma unroll
            for (int nt = 0; nt < 8; nt++) {
                mr0 = fmaxf(mr0, fmaxf(s[nt][0], s[nt][1]));
                mr1 = fmaxf(mr1, fmaxf(s[nt][2], s[nt][3]));
            }
            mr0 = fmaxf(mr0, __shfl_xor_sync(0xffffffffu, mr0, 1));
            mr0 = fmaxf(mr0, __shfl_xor_sync(0xffffffffu, mr0, 2));
            mr1 = fmaxf(mr1, __shfl_xor_sync(0xffffffffu, mr1, 1));
            mr1 = fmaxf(mr1, __shfl_xor_sync(0xffffffffu, mr1, 2));
            const float mn0 = fmaxf(m0, mr0);
            const float mn1 = fmaxf(m1, mr1);
            const float a0 = ex2(m0 - mn0);
            const float a1 = ex2(m1 - mn1);
            m0 = mn0; m1 = mn1;

            // ---- rescale O and lsum ----
#pragma unroll
            for (int nt = 0; nt < 8; nt++) {
                O[nt][0] *= a0; O[nt][1] *= a0;
                O[nt][2] *= a1; O[nt][3] *= a1;
            }
            lsum[0] *= a0; lsum[1] *= a0;
            lsum[2] *= a1; lsum[3] *= a1;

            // ---- P = exp2(s - mn) directly in fp16x2; row sums via MMA ----
#pragma unroll
            for (int ks = 0; ks < 4; ks++) {
                uint32_t ph[4];
                ph[0] = ex2_h2(pack_h2(s[2 * ks][0] - mn0,     s[2 * ks][1] - mn0));
                ph[1] = ex2_h2(pack_h2(s[2 * ks][2] - mn1,     s[2 * ks][3] - mn1));
                ph[2] = ex2_h2(pack_h2(s[2 * ks + 1][0] - mn0, s[2 * ks + 1][1] - mn0));
                ph[3] = ex2_h2(pack_h2(s[2 * ks + 1][2] - mn1, s[2 * ks + 1][3] - mn1));

                MMA_F16(lsum, ph, ONES_H2, ONES_H2);   // exact fp32 row sums

                const int vrow = 16 * ks + (l & 15);
#pragma unroll
                for (int dtp = 0; dtp < 4; dtp++) {
                    uint32_t vf[4];
                    LDMX4T(vf, st + A_VF + aphys(vrow, 2 * dtp + (l >> 4)));
                    MMA_F16(O[2 * dtp + 0], ph, vf[0], vf[1]);
                    MMA_F16(O[2 * dtp + 1], ph, vf[2], vf[3]);
                }
            }
        }

        // ---- epilogue: ctx fp16 ----
        const float i0 = rcp(lsum[0]);
        const float i1 = rcp(lsum[2]);
        const int rg0 = q0 + 16 * w + (l >> 2);
        const int cb = h * 64 + 2 * (l & 3);
#pragma unroll
        for (int nt = 0; nt < 8; nt++) {
            const size_t o0 = (size_t)rg0 * 1024 + cb + nt * 8;
            const size_t o1 = (size_t)(rg0 + 8) * 1024 + cb + nt * 8;
            *(uint32_t*)(g_c + o0) = pack_h2(O[nt][0] * i0, O[nt][1] * i0);
            *(uint32_t*)(g_c + o1) = pack_h2(O[nt][2] * i1, O[nt][3] * i1);
        }
        // Barrier between halves: all warps must finish reading the last KV
        // stage before the next half's prologue overwrites both stages.
        __syncthreads();
    }
}

// ---------------------------------------------------------------------------
extern "C" void kernel_launch(void* const* d_in, const int* in_sizes, int n_in,
                              void* d_out, int out_size)
{
    const float* x  = (const float*)d_in[0];
    const float* Wq = (const float*)d_in[1];
    const float* Wk = (const float*)d_in[2];
    const float* Wv = (const float*)d_in[3];
    const float* Wo = (const float*)d_in[4];
    const float* bo = (const float*)d_in[5];
    float* out = (float*)d_out;

    const int NW = D_MODEL * D_MODEL;     // 1M

    conv_all_kernel<<<dim3(NW / 1024, 8), 256>>>(x, Wq, Wk, Wv, Wo);

    cudaFuncSetAttribute(gemm_qkv_kernel, cudaFuncAttributeMaxDynamicSharedMemorySize, GSMEM);
    cudaFuncSetAttribute(gemm_out_kernel, cudaFuncAttributeMaxDynamicSharedMemorySize, GSMEM);

    gemm_qkv_kernel<<<dim3(24, 32), 256, GSMEM>>>();

    cudaFuncSetAttribute(attn_kernel, cudaFuncAttributeMaxDynamicSharedMemorySize, A_SMEM);
    attn_kernel<<<dim3(32, N_HEADS), 128, A_SMEM>>>();

    gemm_out_kernel<<<dim3(8, 32), 256, GSMEM>>>(bo, out);
}